// round 7
// baseline (speedup 1.0000x reference)
#include <cuda_runtime.h>
#include <cuda_bf16.h>
#include <math.h>
#include <stdint.h>

#define EMBED   1024
#define NHEADS  16
#define HD      64
#define BATCH   4
#define SEQ     2048
#define ROWS    (BATCH * SEQ)          // 8192
#define QKVCOLS (3 * EMBED)            // 3072

// Scratch (allocation-free rule: device globals)
__device__ float g_qkv[(size_t)ROWS * QKVCOLS];   // [B*S, 3E]
__device__ float g_att[(size_t)ROWS * EMBED];     // [B*S, E]

__device__ __forceinline__ float cvt_tf32(float x) {
    float o; asm("cvt.rna.tf32.f32 %0, %1;" : "=f"(o) : "f"(x)); return o;
}
__device__ __forceinline__ uint32_t frag_tf32(float x) {
    return __float_as_uint(cvt_tf32(x));
}
__device__ __forceinline__ uint32_t smem_u32(const void* p) {
    uint32_t a;
    asm("{ .reg .u64 t; cvta.to.shared.u64 t, %1; cvt.u32.u64 %0, t; }" : "=r"(a) : "l"(p));
    return a;
}

#define CP_ASYNC16(dst, src) \
    asm volatile("cp.async.cg.shared.global [%0], [%1], 16;" :: "r"(dst), "l"(src))
#define CP_COMMIT() asm volatile("cp.async.commit_group;" ::: "memory")
#define CP_WAIT0()  asm volatile("cp.async.wait_group 0;" ::: "memory")
#define CP_WAIT1()  asm volatile("cp.async.wait_group 1;" ::: "memory")

// D += A(16x8,row) * B(8x8,col)  tf32
#define MMA_TF32(c0,c1,c2,c3,a0,a1,a2,a3,b0,b1) \
    asm volatile("mma.sync.aligned.m16n8k8.row.col.f32.tf32.tf32.f32 " \
                 "{%0,%1,%2,%3}, {%4,%5,%6,%7}, {%8,%9}, {%0,%1,%2,%3};" \
                 : "+f"(c0), "+f"(c1), "+f"(c2), "+f"(c3) \
                 : "r"(a0), "r"(a1), "r"(a2), "r"(a3), "r"(b0), "r"(b1))

// ============================================================================
// tf32 mma.sync GEMM with cp.async 2-stage pipeline, ALL-STATIC smem.
// C[M,N] = A[M,K] @ W[N,K]^T + bias[N]; CTA 128x128, K-tile 16, 8 warps 4x2.
// Per stage: A 128x20 + B 128x20 floats; 2 stages = 40960 B static.
// Bank check: fragment addr = 20*lq + lr (+const) mod 32 -> all 32 distinct.
// ============================================================================
#define GKT 16
#define TSTRIDE 20
#define GSTAGEF (128 * TSTRIDE)

__global__ __launch_bounds__(256) void gemm_mma_kernel(
    const float* __restrict__ A, const float* __restrict__ W,
    const float* __restrict__ bias, float* __restrict__ C,
    int M, int N, int K)
{
    __shared__ float sA[2][GSTAGEF];
    __shared__ float sB[2][GSTAGEF];

    const int tid    = threadIdx.x;
    const int lane   = tid & 31;
    const int wid    = tid >> 5;
    const int warp_m = wid & 3;
    const int warp_n = wid >> 2;
    const int row0   = blockIdx.y * 128;
    const int col0   = blockIdx.x * 128;

    const int lq = lane >> 2;
    const int lr = lane & 3;

    const uint32_t sbA = smem_u32(&sA[0][0]);
    const uint32_t sbB = smem_u32(&sB[0][0]);

    float c[2][8][4];
#pragma unroll
    for (int mi = 0; mi < 2; mi++)
#pragma unroll
        for (int ni = 0; ni < 8; ni++)
#pragma unroll
            for (int j = 0; j < 4; j++) c[mi][ni][j] = 0.f;

    // per-stage loader: 128 rows x 4 chunks x 2 matrices = 1024 chunks / 256 thr
    auto load_stage = [&](int stg, int k0) {
        uint32_t as = sbA + (uint32_t)stg * (GSTAGEF * 4);
        uint32_t bs = sbB + (uint32_t)stg * (GSTAGEF * 4);
#pragma unroll
        for (int l = 0; l < 2; l++) {
            int f  = tid + l * 256;       // 0..511
            int r  = f >> 2;              // 0..127
            int cc = (f & 3) << 2;        // 0,4,8,12 (floats)
            uint32_t doff = (uint32_t)(r * TSTRIDE + cc) * 4;
            CP_ASYNC16(as + doff, A + (size_t)(row0 + r) * K + k0 + cc);
            CP_ASYNC16(bs + doff, W + (size_t)(col0 + r) * K + k0 + cc);
        }
    };

    const int NKT = K / GKT;      // 64
    load_stage(0, 0);
    CP_COMMIT();

    for (int kt = 0; kt < NKT; kt++) {
        const int buf = kt & 1;
        if (kt + 1 < NKT) {
            load_stage(buf ^ 1, (kt + 1) * GKT);
            CP_COMMIT();
            CP_WAIT1();
        } else {
            CP_WAIT0();
        }
        __syncthreads();

        const float* As = sA[buf];
        const float* Bs = sB[buf];

#pragma unroll
        for (int ks = 0; ks < 2; ks++) {
            const int kk = ks * 8;
            uint32_t a[2][4];
#pragma unroll
            for (int mi = 0; mi < 2; mi++) {
                const float* ab = As + (warp_m * 32 + mi * 16 + lq) * TSTRIDE + kk + lr;
                a[mi][0] = frag_tf32(ab[0]);
                a[mi][1] = frag_tf32(ab[8 * TSTRIDE]);
                a[mi][2] = frag_tf32(ab[4]);
                a[mi][3] = frag_tf32(ab[8 * TSTRIDE + 4]);
            }
            uint32_t b[8][2];
#pragma unroll
            for (int ni = 0; ni < 8; ni++) {
                const float* bb = Bs + (warp_n * 64 + ni * 8 + lq) * TSTRIDE + kk + lr;
                b[ni][0] = frag_tf32(bb[0]);
                b[ni][1] = frag_tf32(bb[4]);
            }
#pragma unroll
            for (int mi = 0; mi < 2; mi++)
#pragma unroll
                for (int ni = 0; ni < 8; ni++)
                    MMA_TF32(c[mi][ni][0], c[mi][ni][1], c[mi][ni][2], c[mi][ni][3],
                             a[mi][0], a[mi][1], a[mi][2], a[mi][3],
                             b[ni][0], b[ni][1]);
        }
        __syncthreads();
    }

#pragma unroll
    for (int mi = 0; mi < 2; mi++) {
        int rg = row0 + warp_m * 32 + mi * 16 + lq;
#pragma unroll
        for (int ni = 0; ni < 8; ni++) {
            int cg = col0 + warp_n * 64 + ni * 8 + 2 * lr;
            float bx = bias[cg], by = bias[cg + 1];
            float2 o0 = make_float2(c[mi][ni][0] + bx, c[mi][ni][1] + by);
            float2 o1 = make_float2(c[mi][ni][2] + bx, c[mi][ni][3] + by);
            *reinterpret_cast<float2*>(C + (size_t)rg * N + cg) = o0;
            *reinterpret_cast<float2*>(C + (size_t)(rg + 8) * N + cg) = o1;
        }
    }
}

// ============================================================================
// Tensor-core flash attention (tf32 mma.sync) — exact R5 version (static smem).
// CTA: 256 thr = 8 warps, 128 q-rows of one (b,h); warp w owns rows 16w..16w+15.
// ============================================================================
#define KSTR 68
#define PSTR 36

__global__ __launch_bounds__(256) void attn_mma_kernel(const float* __restrict__ qkv,
                                                       float* __restrict__ att)
{
    __shared__ float sm[8960];

    const int tid  = threadIdx.x;
    const int lane = tid & 31;
    const int w    = tid >> 5;        // 0..7
    const int lq   = lane >> 2;       // 0..7
    const int lr   = lane & 3;        // 0..3

    const int qt = blockIdx.x;        // 0..15
    const int bh = blockIdx.y;
    const int b  = bh >> 4;
    const int h  = bh & 15;

    const size_t rs = QKVCOLS;
    const float* base = qkv + (size_t)b * SEQ * rs + h * (3 * HD);

    // ---- stage Q tile [128][64] -> sm (stride 68), scaled + tf32 ----
#pragma unroll
    for (int l = 0; l < 8; l++) {
        int f = tid + l * 256;
        int r = f >> 4;
        int c = (f & 15) << 2;
        float4 v = *reinterpret_cast<const float4*>(base + (size_t)(qt * 128 + r) * rs + c);
        float* qp = sm + r * KSTR + c;
        qp[0] = cvt_tf32(v.x * 0.125f); qp[1] = cvt_tf32(v.y * 0.125f);
        qp[2] = cvt_tf32(v.z * 0.125f); qp[3] = cvt_tf32(v.w * 0.125f);
    }
    __syncthreads();

    uint32_t aq[8][4];
    {
        const float* qb = sm + (w * 16 + lq) * KSTR;
#pragma unroll
        for (int kk = 0; kk < 8; kk++) {
            aq[kk][0] = __float_as_uint(qb[kk * 8 + lr]);
            aq[kk][1] = __float_as_uint(qb[8 * KSTR + kk * 8 + lr]);
            aq[kk][2] = __float_as_uint(qb[kk * 8 + lr + 4]);
            aq[kk][3] = __float_as_uint(qb[8 * KSTR + kk * 8 + lr + 4]);
        }
    }
    __syncthreads();

    float* Ks  = sm;                       // [32][68]
    float* Vs  = sm + 32 * KSTR;           // [32][68]
    float* Psw = sm + 64 * KSTR + w * 16 * PSTR;   // per-warp [16][36]

    float o[8][4];
#pragma unroll
    for (int ni = 0; ni < 8; ni++)
#pragma unroll
        for (int j = 0; j < 4; j++) o[ni][j] = 0.f;
    float m0 = -INFINITY, m1 = -INFINITY, l0 = 0.f, l1 = 0.f;

    for (int kt = 0; kt < SEQ / 32; kt++) {
#pragma unroll
        for (int l = 0; l < 2; l++) {
            int f = tid + l * 256;
            int r = f >> 4;
            int c = (f & 15) << 2;
            const float* kr = base + 64 + (size_t)(kt * 32 + r) * rs + c;
            float4 kv4 = *reinterpret_cast<const float4*>(kr);
            float* kp = Ks + r * KSTR + c;
            kp[0] = cvt_tf32(kv4.x); kp[1] = cvt_tf32(kv4.y);
            kp[2] = cvt_tf32(kv4.z); kp[3] = cvt_tf32(kv4.w);
            float4 vv4 = *reinterpret_cast<const float4*>(kr + 64);
            float* vp = Vs + r * KSTR + c;
            vp[0] = cvt_tf32(vv4.x); vp[1] = cvt_tf32(vv4.y);
            vp[2] = cvt_tf32(vv4.z); vp[3] = cvt_tf32(vv4.w);
        }
        __syncthreads();

        // ---- S = Q K^T ----
        float s[4][4];
#pragma unroll
        for (int ni = 0; ni < 4; ni++)
#pragma unroll
            for (int j = 0; j < 4; j++) s[ni][j] = 0.f;

#pragma unroll
        for (int kk = 0; kk < 8; kk++) {
            uint32_t bk[4][2];
#pragma unroll
            for (int ni = 0; ni < 4; ni++) {
                const float* kb = Ks + (ni * 8 + lq) * KSTR + kk * 8 + lr;
                bk[ni][0] = __float_as_uint(kb[0]);
                bk[ni][1] = __float_as_uint(kb[4]);
            }
#pragma unroll
            for (int ni = 0; ni < 4; ni++)
                MMA_TF32(s[ni][0], s[ni][1], s[ni][2], s[ni][3],
                         aq[kk][0], aq[kk][1], aq[kk][2], aq[kk][3],
                         bk[ni][0], bk[ni][1]);
        }

        // ---- online softmax on fragments (rows lq, lq+8) ----
        float mx0 = -INFINITY, mx1 = -INFINITY;
#pragma unroll
        for (int ni = 0; ni < 4; ni++) {
            mx0 = fmaxf(mx0, fmaxf(s[ni][0], s[ni][1]));
            mx1 = fmaxf(mx1, fmaxf(s[ni][2], s[ni][3]));
        }
        mx0 = fmaxf(mx0, __shfl_xor_sync(0xffffffffu, mx0, 1));
        mx0 = fmaxf(mx0, __shfl_xor_sync(0xffffffffu, mx0, 2));
        mx1 = fmaxf(mx1, __shfl_xor_sync(0xffffffffu, mx1, 1));
        mx1 = fmaxf(mx1, __shfl_xor_sync(0xffffffffu, mx1, 2));

        float mn0 = fmaxf(m0, mx0);
        float mn1 = fmaxf(m1, mx1);
        float corr0 = __expf(m0 - mn0);
        float corr1 = __expf(m1 - mn1);
        m0 = mn0; m1 = mn1;

        float sum0 = 0.f, sum1 = 0.f;
#pragma unroll
        for (int ni = 0; ni < 4; ni++) {
            float p0 = __expf(s[ni][0] - m0);
            float p1 = __expf(s[ni][1] - m0);
            float p2 = __expf(s[ni][2] - m1);
            float p3 = __expf(s[ni][3] - m1);
            sum0 += p0 + p1;
            sum1 += p2 + p3;
            *reinterpret_cast<float2*>(Psw + lq * PSTR + ni * 8 + 2 * lr) =
                make_float2(cvt_tf32(p0), cvt_tf32(p1));
            *reinterpret_cast<float2*>(Psw + (lq + 8) * PSTR + ni * 8 + 2 * lr) =
                make_float2(cvt_tf32(p2), cvt_tf32(p3));
        }
        sum0 += __shfl_xor_sync(0xffffffffu, sum0, 1);
        sum0 += __shfl_xor_sync(0xffffffffu, sum0, 2);
        sum1 += __shfl_xor_sync(0xffffffffu, sum1, 1);
        sum1 += __shfl_xor_sync(0xffffffffu, sum1, 2);
        l0 = l0 * corr0 + sum0;
        l1 = l1 * corr1 + sum1;

#pragma unroll
        for (int ni = 0; ni < 8; ni++) {
            o[ni][0] *= corr0; o[ni][1] *= corr0;
            o[ni][2] *= corr1; o[ni][3] *= corr1;
        }
        __syncwarp();

        // ---- O += P V ----
#pragma unroll
        for (int kk = 0; kk < 4; kk++) {
            uint32_t pa[4];
            const float* pb = Psw + lq * PSTR + kk * 8 + lr;
            pa[0] = __float_as_uint(pb[0]);
            pa[1] = __float_as_uint(pb[8 * PSTR]);
            pa[2] = __float_as_uint(pb[4]);
            pa[3] = __float_as_uint(pb[8 * PSTR + 4]);
#pragma unroll
            for (int ni = 0; ni < 8; ni++) {
                uint32_t vb0 = __float_as_uint(Vs[(kk * 8 + lr) * KSTR + ni * 8 + lq]);
                uint32_t vb1 = __float_as_uint(Vs[(kk * 8 + lr + 4) * KSTR + ni * 8 + lq]);
                MMA_TF32(o[ni][0], o[ni][1], o[ni][2], o[ni][3],
                         pa[0], pa[1], pa[2], pa[3], vb0, vb1);
            }
        }
        __syncthreads();
    }

    // ---- finalize + write ----
    float inv0 = 1.f / l0;
    float inv1 = 1.f / l1;
    int gq = qt * 128 + w * 16 + lq;
    float* orow0 = att + (size_t)(b * SEQ + gq) * EMBED + h * HD;
    float* orow1 = orow0 + (size_t)8 * EMBED;
#pragma unroll
    for (int ni = 0; ni < 8; ni++) {
        int col = ni * 8 + 2 * lr;
        *reinterpret_cast<float2*>(orow0 + col) =
            make_float2(o[ni][0] * inv0, o[ni][1] * inv0);
        *reinterpret_cast<float2*>(orow1 + col) =
            make_float2(o[ni][2] * inv1, o[ni][3] * inv1);
    }
}

// ---------------------------------------------------------------------------
extern "C" void kernel_launch(void* const* d_in, const int* in_sizes, int n_in,
                              void* d_out, int out_size)
{
    (void)in_sizes; (void)n_in; (void)out_size;
    const float* x     = (const float*)d_in[0];
    const float* qkv_w = (const float*)d_in[1];
    const float* qkv_b = (const float*)d_in[2];
    const float* out_w = (const float*)d_in[3];
    const float* out_b = (const float*)d_in[4];
    float* out = (float*)d_out;

    float *qkv_buf, *att_buf;
    cudaGetSymbolAddress((void**)&qkv_buf, g_qkv);
    cudaGetSymbolAddress((void**)&att_buf, g_att);

    // 1) qkv = x @ qkv_w^T + qkv_b    [8192, 3072]
    gemm_mma_kernel<<<dim3(QKVCOLS / 128, ROWS / 128), 256>>>(
        x, qkv_w, qkv_b, qkv_buf, ROWS, QKVCOLS, EMBED);

    // 2) attention -> att [8192, 1024]
    attn_mma_kernel<<<dim3(SEQ / 128, BATCH * NHEADS), 256>>>(qkv_buf, att_buf);

    // 3) out = att @ out_w^T + out_b  [8192, 1024]
    gemm_mma_kernel<<<dim3(EMBED / 128, ROWS / 128), 256>>>(
        att_buf, out_w, out_b, out, ROWS, EMBED, EMBED);
}

// round 8
// speedup vs baseline: 1.0070x; 1.0070x over previous
#include <cuda_runtime.h>
#include <cuda_bf16.h>
#include <math.h>
#include <stdint.h>

#define EMBED   1024
#define NHEADS  16
#define HD      64
#define BATCH   4
#define SEQ     2048
#define ROWS    (BATCH * SEQ)          // 8192
#define QKVCOLS (3 * EMBED)            // 3072

// Scratch (allocation-free rule: device globals)
__device__ float g_qkv[(size_t)ROWS * QKVCOLS];   // [B*S, 3E]
__device__ float g_att[(size_t)ROWS * EMBED];     // [B*S, E] (tf32-rounded)
__device__ float g_xr[(size_t)ROWS * EMBED];      // tf32-rounded x
__device__ float g_wqkv[(size_t)QKVCOLS * EMBED]; // tf32-rounded qkv_w
__device__ float g_wout[(size_t)EMBED * EMBED];   // tf32-rounded out_w

__device__ __forceinline__ float cvt_tf32(float x) {
    float o; asm("cvt.rna.tf32.f32 %0, %1;" : "=f"(o) : "f"(x)); return o;
}
__device__ __forceinline__ uint32_t smem_u32(const void* p) {
    uint32_t a;
    asm("{ .reg .u64 t; cvta.to.shared.u64 t, %1; cvt.u32.u64 %0, t; }" : "=r"(a) : "l"(p));
    return a;
}

#define CP_ASYNC16(dst, src) \
    asm volatile("cp.async.cg.shared.global [%0], [%1], 16;" :: "r"(dst), "l"(src))
#define CP_COMMIT() asm volatile("cp.async.commit_group;" ::: "memory")
#define CP_WAIT0()  asm volatile("cp.async.wait_group 0;" ::: "memory")

// D += A(16x8,row) * B(8x8,col)  tf32
#define MMA_TF32(c0,c1,c2,c3,a0,a1,a2,a3,b0,b1) \
    asm volatile("mma.sync.aligned.m16n8k8.row.col.f32.tf32.tf32.f32 " \
                 "{%0,%1,%2,%3}, {%4,%5,%6,%7}, {%8,%9}, {%0,%1,%2,%3};" \
                 : "+f"(c0), "+f"(c1), "+f"(c2), "+f"(c3) \
                 : "r"(a0), "r"(a1), "r"(a2), "r"(a3), "r"(b0), "r"(b1))

// ============================================================================
// Pre-round fp32 -> tf32(rna) stored as fp32. Grid-stride float4.
// ============================================================================
__global__ __launch_bounds__(256) void round_tf32_kernel(
    const float* __restrict__ src, float* __restrict__ dst, int n4)
{
    int i = blockIdx.x * blockDim.x + threadIdx.x;
    int stride = gridDim.x * blockDim.x;
    for (; i < n4; i += stride) {
        float4 v = reinterpret_cast<const float4*>(src)[i];
        v.x = cvt_tf32(v.x); v.y = cvt_tf32(v.y);
        v.z = cvt_tf32(v.z); v.w = cvt_tf32(v.w);
        reinterpret_cast<float4*>(dst)[i] = v;
    }
}

// ============================================================================
// tf32 mma.sync GEMM, cp.async 2-stage, pre-rounded inputs, 1 sync/iter.
// C[M,N] = A[M,K] @ W[N,K]^T + bias[N]; CTA 128x128, K-tile 16, 8 warps 4x2.
// Static smem: 2 stages x (A+B) 128x20 floats = 40960 B.
// ============================================================================
#define GKT 16
#define TSTRIDE 20
#define GSTAGEF (128 * TSTRIDE)

__global__ __launch_bounds__(256) void gemm_mma_kernel(
    const float* __restrict__ A, const float* __restrict__ W,
    const float* __restrict__ bias, float* __restrict__ C,
    int M, int N, int K)
{
    __shared__ float sA[2][GSTAGEF];
    __shared__ float sB[2][GSTAGEF];

    const int tid    = threadIdx.x;
    const int lane   = tid & 31;
    const int wid    = tid >> 5;
    const int warp_m = wid & 3;
    const int warp_n = wid >> 2;
    const int row0   = blockIdx.y * 128;
    const int col0   = blockIdx.x * 128;

    const int lq = lane >> 2;
    const int lr = lane & 3;

    const uint32_t sbA = smem_u32(&sA[0][0]);
    const uint32_t sbB = smem_u32(&sB[0][0]);

    float c[2][8][4];
#pragma unroll
    for (int mi = 0; mi < 2; mi++)
#pragma unroll
        for (int ni = 0; ni < 8; ni++)
#pragma unroll
            for (int j = 0; j < 4; j++) c[mi][ni][j] = 0.f;

    auto load_stage = [&](int stg, int k0) {
        uint32_t as = sbA + (uint32_t)stg * (GSTAGEF * 4);
        uint32_t bs = sbB + (uint32_t)stg * (GSTAGEF * 4);
#pragma unroll
        for (int l = 0; l < 2; l++) {
            int f  = tid + l * 256;       // 0..511
            int r  = f >> 2;              // 0..127
            int cc = (f & 3) << 2;        // 0,4,8,12 (floats)
            uint32_t doff = (uint32_t)(r * TSTRIDE + cc) * 4;
            CP_ASYNC16(as + doff, A + (size_t)(row0 + r) * K + k0 + cc);
            CP_ASYNC16(bs + doff, W + (size_t)(col0 + r) * K + k0 + cc);
        }
    };

    const int NKT = K / GKT;      // 64
    load_stage(0, 0);
    CP_COMMIT();

    for (int kt = 0; kt < NKT; kt++) {
        const int buf = kt & 1;
        CP_WAIT0();               // stage kt landed
        __syncthreads();          // all threads done with buf^1's compute
        if (kt + 1 < NKT) {
            load_stage(buf ^ 1, (kt + 1) * GKT);
            CP_COMMIT();
        }

        const float* As = sA[buf];
        const float* Bs = sB[buf];

#pragma unroll
        for (int ks = 0; ks < 2; ks++) {
            const int kk = ks * 8;
            uint32_t a[2][4];
#pragma unroll
            for (int mi = 0; mi < 2; mi++) {
                const float* ab = As + (warp_m * 32 + mi * 16 + lq) * TSTRIDE + kk + lr;
                a[mi][0] = __float_as_uint(ab[0]);
                a[mi][1] = __float_as_uint(ab[8 * TSTRIDE]);
                a[mi][2] = __float_as_uint(ab[4]);
                a[mi][3] = __float_as_uint(ab[8 * TSTRIDE + 4]);
            }
            uint32_t b[8][2];
#pragma unroll
            for (int ni = 0; ni < 8; ni++) {
                const float* bb = Bs + (warp_n * 64 + ni * 8 + lq) * TSTRIDE + kk + lr;
                b[ni][0] = __float_as_uint(bb[0]);
                b[ni][1] = __float_as_uint(bb[4]);
            }
#pragma unroll
            for (int mi = 0; mi < 2; mi++)
#pragma unroll
                for (int ni = 0; ni < 8; ni++)
                    MMA_TF32(c[mi][ni][0], c[mi][ni][1], c[mi][ni][2], c[mi][ni][3],
                             a[mi][0], a[mi][1], a[mi][2], a[mi][3],
                             b[ni][0], b[ni][1]);
        }
        __syncthreads();          // compute(buf) done before next load overwrites
    }

#pragma unroll
    for (int mi = 0; mi < 2; mi++) {
        int rg = row0 + warp_m * 32 + mi * 16 + lq;
#pragma unroll
        for (int ni = 0; ni < 8; ni++) {
            int cg = col0 + warp_n * 64 + ni * 8 + 2 * lr;
            float bx = bias[cg], by = bias[cg + 1];
            float2 o0 = make_float2(c[mi][ni][0] + bx, c[mi][ni][1] + by);
            float2 o1 = make_float2(c[mi][ni][2] + bx, c[mi][ni][3] + by);
            *reinterpret_cast<float2*>(C + (size_t)rg * N + cg) = o0;
            *reinterpret_cast<float2*>(C + (size_t)(rg + 8) * N + cg) = o1;
        }
    }
}

// ============================================================================
// Tensor-core flash attention (tf32 mma.sync) — proven R5/R7 version.
// Output write is tf32-rounded so GEMM3 needs no conversion.
// ============================================================================
#define KSTR 68
#define PSTR 36

__global__ __launch_bounds__(256) void attn_mma_kernel(const float* __restrict__ qkv,
                                                       float* __restrict__ att)
{
    __shared__ float sm[8960];

    const int tid  = threadIdx.x;
    const int lane = tid & 31;
    const int w    = tid >> 5;
    const int lq   = lane >> 2;
    const int lr   = lane & 3;

    const int qt = blockIdx.x;
    const int bh = blockIdx.y;
    const int b  = bh >> 4;
    const int h  = bh & 15;

    const size_t rs = QKVCOLS;
    const float* base = qkv + (size_t)b * SEQ * rs + h * (3 * HD);

#pragma unroll
    for (int l = 0; l < 8; l++) {
        int f = tid + l * 256;
        int r = f >> 4;
        int c = (f & 15) << 2;
        float4 v = *reinterpret_cast<const float4*>(base + (size_t)(qt * 128 + r) * rs + c);
        float* qp = sm + r * KSTR + c;
        qp[0] = cvt_tf32(v.x * 0.125f); qp[1] = cvt_tf32(v.y * 0.125f);
        qp[2] = cvt_tf32(v.z * 0.125f); qp[3] = cvt_tf32(v.w * 0.125f);
    }
    __syncthreads();

    uint32_t aq[8][4];
    {
        const float* qb = sm + (w * 16 + lq) * KSTR;
#pragma unroll
        for (int kk = 0; kk < 8; kk++) {
            aq[kk][0] = __float_as_uint(qb[kk * 8 + lr]);
            aq[kk][1] = __float_as_uint(qb[8 * KSTR + kk * 8 + lr]);
            aq[kk][2] = __float_as_uint(qb[kk * 8 + lr + 4]);
            aq[kk][3] = __float_as_uint(qb[8 * KSTR + kk * 8 + lr + 4]);
        }
    }
    __syncthreads();

    float* Ks  = sm;
    float* Vs  = sm + 32 * KSTR;
    float* Psw = sm + 64 * KSTR + w * 16 * PSTR;

    float o[8][4];
#pragma unroll
    for (int ni = 0; ni < 8; ni++)
#pragma unroll
        for (int j = 0; j < 4; j++) o[ni][j] = 0.f;
    float m0 = -INFINITY, m1 = -INFINITY, l0 = 0.f, l1 = 0.f;

    for (int kt = 0; kt < SEQ / 32; kt++) {
#pragma unroll
        for (int l = 0; l < 2; l++) {
            int f = tid + l * 256;
            int r = f >> 4;
            int c = (f & 15) << 2;
            const float* kr = base + 64 + (size_t)(kt * 32 + r) * rs + c;
            float4 kv4 = *reinterpret_cast<const float4*>(kr);
            float* kp = Ks + r * KSTR + c;
            kp[0] = cvt_tf32(kv4.x); kp[1] = cvt_tf32(kv4.y);
            kp[2] = cvt_tf32(kv4.z); kp[3] = cvt_tf32(kv4.w);
            float4 vv4 = *reinterpret_cast<const float4*>(kr + 64);
            float* vp = Vs + r * KSTR + c;
            vp[0] = cvt_tf32(vv4.x); vp[1] = cvt_tf32(vv4.y);
            vp[2] = cvt_tf32(vv4.z); vp[3] = cvt_tf32(vv4.w);
        }
        __syncthreads();

        float s[4][4];
#pragma unroll
        for (int ni = 0; ni < 4; ni++)
#pragma unroll
            for (int j = 0; j < 4; j++) s[ni][j] = 0.f;

#pragma unroll
        for (int kk = 0; kk < 8; kk++) {
            uint32_t bk[4][2];
#pragma unroll
            for (int ni = 0; ni < 4; ni++) {
                const float* kb = Ks + (ni * 8 + lq) * KSTR + kk * 8 + lr;
                bk[ni][0] = __float_as_uint(kb[0]);
                bk[ni][1] = __float_as_uint(kb[4]);
            }
#pragma unroll
            for (int ni = 0; ni < 4; ni++)
                MMA_TF32(s[ni][0], s[ni][1], s[ni][2], s[ni][3],
                         aq[kk][0], aq[kk][1], aq[kk][2], aq[kk][3],
                         bk[ni][0], bk[ni][1]);
        }

        float mx0 = -INFINITY, mx1 = -INFINITY;
#pragma unroll
        for (int ni = 0; ni < 4; ni++) {
            mx0 = fmaxf(mx0, fmaxf(s[ni][0], s[ni][1]));
            mx1 = fmaxf(mx1, fmaxf(s[ni][2], s[ni][3]));
        }
        mx0 = fmaxf(mx0, __shfl_xor_sync(0xffffffffu, mx0, 1));
        mx0 = fmaxf(mx0, __shfl_xor_sync(0xffffffffu, mx0, 2));
        mx1 = fmaxf(mx1, __shfl_xor_sync(0xffffffffu, mx1, 1));
        mx1 = fmaxf(mx1, __shfl_xor_sync(0xffffffffu, mx1, 2));

        float mn0 = fmaxf(m0, mx0);
        float mn1 = fmaxf(m1, mx1);
        float corr0 = __expf(m0 - mn0);
        float corr1 = __expf(m1 - mn1);
        m0 = mn0; m1 = mn1;

        float sum0 = 0.f, sum1 = 0.f;
#pragma unroll
        for (int ni = 0; ni < 4; ni++) {
            float p0 = __expf(s[ni][0] - m0);
            float p1 = __expf(s[ni][1] - m0);
            float p2 = __expf(s[ni][2] - m1);
            float p3 = __expf(s[ni][3] - m1);
            sum0 += p0 + p1;
            sum1 += p2 + p3;
            *reinterpret_cast<float2*>(Psw + lq * PSTR + ni * 8 + 2 * lr) =
                make_float2(cvt_tf32(p0), cvt_tf32(p1));
            *reinterpret_cast<float2*>(Psw + (lq + 8) * PSTR + ni * 8 + 2 * lr) =
                make_float2(cvt_tf32(p2), cvt_tf32(p3));
        }
        sum0 += __shfl_xor_sync(0xffffffffu, sum0, 1);
        sum0 += __shfl_xor_sync(0xffffffffu, sum0, 2);
        sum1 += __shfl_xor_sync(0xffffffffu, sum1, 1);
        sum1 += __shfl_xor_sync(0xffffffffu, sum1, 2);
        l0 = l0 * corr0 + sum0;
        l1 = l1 * corr1 + sum1;

#pragma unroll
        for (int ni = 0; ni < 8; ni++) {
            o[ni][0] *= corr0; o[ni][1] *= corr0;
            o[ni][2] *= corr1; o[ni][3] *= corr1;
        }
        __syncwarp();

#pragma unroll
        for (int kk = 0; kk < 4; kk++) {
            uint32_t pa[4];
            const float* pb = Psw + lq * PSTR + kk * 8 + lr;
            pa[0] = __float_as_uint(pb[0]);
            pa[1] = __float_as_uint(pb[8 * PSTR]);
            pa[2] = __float_as_uint(pb[4]);
            pa[3] = __float_as_uint(pb[8 * PSTR + 4]);
#pragma unroll
            for (int ni = 0; ni < 8; ni++) {
                uint32_t vb0 = __float_as_uint(Vs[(kk * 8 + lr) * KSTR + ni * 8 + lq]);
                uint32_t vb1 = __float_as_uint(Vs[(kk * 8 + lr + 4) * KSTR + ni * 8 + lq]);
                MMA_TF32(o[ni][0], o[ni][1], o[ni][2], o[ni][3],
                         pa[0], pa[1], pa[2], pa[3], vb0, vb1);
            }
        }
        __syncthreads();
    }

    // ---- finalize + write (tf32-rounded for GEMM3's pre-rounded A) ----
    float inv0 = 1.f / l0;
    float inv1 = 1.f / l1;
    int gq = qt * 128 + w * 16 + lq;
    float* orow0 = att + (size_t)(b * SEQ + gq) * EMBED + h * HD;
    float* orow1 = orow0 + (size_t)8 * EMBED;
#pragma unroll
    for (int ni = 0; ni < 8; ni++) {
        int col = ni * 8 + 2 * lr;
        *reinterpret_cast<float2*>(orow0 + col) =
            make_float2(cvt_tf32(o[ni][0] * inv0), cvt_tf32(o[ni][1] * inv0));
        *reinterpret_cast<float2*>(orow1 + col) =
            make_float2(cvt_tf32(o[ni][2] * inv1), cvt_tf32(o[ni][3] * inv1));
    }
}

// ---------------------------------------------------------------------------
extern "C" void kernel_launch(void* const* d_in, const int* in_sizes, int n_in,
                              void* d_out, int out_size)
{
    (void)in_sizes; (void)n_in; (void)out_size;
    const float* x     = (const float*)d_in[0];
    const float* qkv_w = (const float*)d_in[1];
    const float* qkv_b = (const float*)d_in[2];
    const float* out_w = (const float*)d_in[3];
    const float* out_b = (const float*)d_in[4];
    float* out = (float*)d_out;

    float *qkv_buf, *att_buf, *xr, *wqkv, *wout;
    cudaGetSymbolAddress((void**)&qkv_buf, g_qkv);
    cudaGetSymbolAddress((void**)&att_buf, g_att);
    cudaGetSymbolAddress((void**)&xr, g_xr);
    cudaGetSymbolAddress((void**)&wqkv, g_wqkv);
    cudaGetSymbolAddress((void**)&wout, g_wout);

    // 0) pre-round inputs to tf32
    round_tf32_kernel<<<512, 256>>>(x, xr, ROWS * EMBED / 4);
    round_tf32_kernel<<<512, 256>>>(qkv_w, wqkv, QKVCOLS * EMBED / 4);
    round_tf32_kernel<<<512, 256>>>(out_w, wout, EMBED * EMBED / 4);

    // 1) qkv = x @ qkv_w^T + qkv_b    [8192, 3072]
    gemm_mma_kernel<<<dim3(QKVCOLS / 128, ROWS / 128), 256>>>(
        xr, wqkv, qkv_b, qkv_buf, ROWS, QKVCOLS, EMBED);

    // 2) attention -> att [8192, 1024] (tf32-rounded output)
    attn_mma_kernel<<<dim3(SEQ / 128, BATCH * NHEADS), 256>>>(qkv_buf, att_buf);

    // 3) out = att @ out_w^T + out_b  [8192, 1024]
    gemm_mma_kernel<<<dim3(EMBED / 128, ROWS / 128), 256>>>(
        att_buf, wout, out_b, out, ROWS, EMBED, EMBED);
}

// round 12
// speedup vs baseline: 1.1941x; 1.1858x over previous
#include <cuda_runtime.h>
#include <cuda_bf16.h>
#include <math.h>
#include <stdint.h>

#define EMBED   1024
#define NHEADS  16
#define HD      64
#define BATCH   4
#define SEQ     2048
#define ROWS    (BATCH * SEQ)          // 8192
#define QKVCOLS (3 * EMBED)            // 3072

// Scratch (allocation-free rule: device globals)
__device__ float g_qkv[(size_t)ROWS * QKVCOLS];   // [B*S, 3E], tf32-rounded
__device__ float g_att[(size_t)ROWS * EMBED];     // [B*S, E], tf32-rounded

__device__ __forceinline__ float cvt_tf32(float x) {
    float o; asm("cvt.rna.tf32.f32 %0, %1;" : "=f"(o) : "f"(x)); return o;
}
__device__ __forceinline__ uint32_t smem_u32(const void* p) {
    uint32_t a;
    asm("{ .reg .u64 t; cvta.to.shared.u64 t, %1; cvt.u32.u64 %0, t; }" : "=r"(a) : "l"(p));
    return a;
}

#define CP_ASYNC16(dst, src) \
    asm volatile("cp.async.cg.shared.global [%0], [%1], 16;" :: "r"(dst), "l"(src))
#define CP_COMMIT() asm volatile("cp.async.commit_group;" ::: "memory")
#define CP_WAIT0()  asm volatile("cp.async.wait_group 0;" ::: "memory")

// D += A(16x8,row) * B(8x8,col)  tf32
#define MMA_TF32(c0,c1,c2,c3,a0,a1,a2,a3,b0,b1) \
    asm volatile("mma.sync.aligned.m16n8k8.row.col.f32.tf32.tf32.f32 " \
                 "{%0,%1,%2,%3}, {%4,%5,%6,%7}, {%8,%9}, {%0,%1,%2,%3};" \
                 : "+f"(c0), "+f"(c1), "+f"(c2), "+f"(c3) \
                 : "r"(a0), "r"(a1), "r"(a2), "r"(a3), "r"(b0), "r"(b1))

// ============================================================================
// tf32 mma.sync GEMM (R5-proven form): C = A @ W^T + bias.
// CTA 128x128, K-tile 32, sync loader with cvt. round_out: tf32-round C.
// ============================================================================
#define GKT 32
#define TSTRIDE 36

__global__ __launch_bounds__(256) void gemm_mma_kernel(
    const float* __restrict__ A, const float* __restrict__ W,
    const float* __restrict__ bias, float* __restrict__ C,
    int M, int N, int K, int round_out)
{
    __shared__ float As[128 * TSTRIDE];
    __shared__ float Bs[128 * TSTRIDE];

    const int tid    = threadIdx.x;
    const int lane   = tid & 31;
    const int wid    = tid >> 5;
    const int warp_m = wid & 3;
    const int warp_n = wid >> 2;
    const int row0   = blockIdx.y * 128;
    const int col0   = blockIdx.x * 128;

    const int lq = lane >> 2;
    const int lr = lane & 3;

    float c[2][8][4];
#pragma unroll
    for (int mi = 0; mi < 2; mi++)
#pragma unroll
        for (int ni = 0; ni < 8; ni++)
#pragma unroll
            for (int j = 0; j < 4; j++) c[mi][ni][j] = 0.f;

    const int NKT = K / GKT;
    for (int kt = 0; kt < NKT; kt++) {
        if (kt > 0) __syncthreads();
        const int k0 = kt * GKT;
#pragma unroll
        for (int l = 0; l < 4; l++) {
            int f = tid + l * 256;
            int r = f >> 3;
            int c4 = (f & 7) << 2;
            float4 va = *reinterpret_cast<const float4*>(A + (size_t)(row0 + r) * K + k0 + c4);
            float* ap = As + r * TSTRIDE + c4;
            ap[0] = cvt_tf32(va.x); ap[1] = cvt_tf32(va.y);
            ap[2] = cvt_tf32(va.z); ap[3] = cvt_tf32(va.w);
            float4 vb = *reinterpret_cast<const float4*>(W + (size_t)(col0 + r) * K + k0 + c4);
            float* bp = Bs + r * TSTRIDE + c4;
            bp[0] = cvt_tf32(vb.x); bp[1] = cvt_tf32(vb.y);
            bp[2] = cvt_tf32(vb.z); bp[3] = cvt_tf32(vb.w);
        }
        __syncthreads();

#pragma unroll
        for (int ks = 0; ks < 4; ks++) {
            const int kk = ks * 8;
            uint32_t a[2][4];
#pragma unroll
            for (int mi = 0; mi < 2; mi++) {
                const float* ab = As + (warp_m * 32 + mi * 16 + lq) * TSTRIDE + kk + lr;
                a[mi][0] = __float_as_uint(ab[0]);
                a[mi][1] = __float_as_uint(ab[8 * TSTRIDE]);
                a[mi][2] = __float_as_uint(ab[4]);
                a[mi][3] = __float_as_uint(ab[8 * TSTRIDE + 4]);
            }
            uint32_t b[8][2];
#pragma unroll
            for (int ni = 0; ni < 8; ni++) {
                const float* bb = Bs + (warp_n * 64 + ni * 8 + lq) * TSTRIDE + kk + lr;
                b[ni][0] = __float_as_uint(bb[0]);
                b[ni][1] = __float_as_uint(bb[4]);
            }
#pragma unroll
            for (int mi = 0; mi < 2; mi++)
#pragma unroll
                for (int ni = 0; ni < 8; ni++)
                    MMA_TF32(c[mi][ni][0], c[mi][ni][1], c[mi][ni][2], c[mi][ni][3],
                             a[mi][0], a[mi][1], a[mi][2], a[mi][3],
                             b[ni][0], b[ni][1]);
        }
    }

#pragma unroll
    for (int mi = 0; mi < 2; mi++) {
        int rg = row0 + warp_m * 32 + mi * 16 + lq;
#pragma unroll
        for (int ni = 0; ni < 8; ni++) {
            int cg = col0 + warp_n * 64 + ni * 8 + 2 * lr;
            float bx = bias[cg], by = bias[cg + 1];
            float2 o0 = make_float2(c[mi][ni][0] + bx, c[mi][ni][1] + by);
            float2 o1 = make_float2(c[mi][ni][2] + bx, c[mi][ni][3] + by);
            if (round_out) {
                o0.x = cvt_tf32(o0.x); o0.y = cvt_tf32(o0.y);
                o1.x = cvt_tf32(o1.x); o1.y = cvt_tf32(o1.y);
            }
            *reinterpret_cast<float2*>(C + (size_t)rg * N + cg) = o0;
            *reinterpret_cast<float2*>(C + (size_t)(rg + 8) * N + cg) = o1;
        }
    }
}

// ============================================================================
// Tensor-core flash attention, cp.async 2-stage K/V, shfl-transposed P (no P
// smem). qkv is tf32-pre-rounded by GEMM1. CTA: 8 warps, 128 q-rows, kv=32.
// Static smem: 2 stages x (K 32x68 + V 32x68) = 34816 B (Q staging aliased).
// ============================================================================
#define KSTR 68
#define KVSTG (2 * 32 * KSTR)       // floats per stage (K+V) = 4352

__global__ __launch_bounds__(256) void attn_mma_kernel(const float* __restrict__ qkv,
                                                       float* __restrict__ att)
{
    __shared__ float sm[2 * KVSTG];     // 8704 floats

    const int tid  = threadIdx.x;
    const int lane = tid & 31;
    const int w    = tid >> 5;
    const int lq   = lane >> 2;
    const int lr   = lane & 3;

    const int qt = blockIdx.x;
    const int bh = blockIdx.y;
    const int b  = bh >> 4;
    const int h  = bh & 15;

    const size_t rs = QKVCOLS;
    const float* base = qkv + (size_t)b * SEQ * rs + h * (3 * HD);

    // ---- stage Q tile [128][64] (qkv already tf32; *0.125 is exact) ----
#pragma unroll
    for (int l = 0; l < 8; l++) {
        int f = tid + l * 256;
        int r = f >> 4;
        int c = (f & 15) << 2;
        float4 v = *reinterpret_cast<const float4*>(base + (size_t)(qt * 128 + r) * rs + c);
        float* qp = sm + r * KSTR + c;
        qp[0] = v.x * 0.125f; qp[1] = v.y * 0.125f;
        qp[2] = v.z * 0.125f; qp[3] = v.w * 0.125f;
    }
    __syncthreads();

    uint32_t aq[8][4];
    {
        const float* qb = sm + (w * 16 + lq) * KSTR;
#pragma unroll
        for (int kk = 0; kk < 8; kk++) {
            aq[kk][0] = __float_as_uint(qb[kk * 8 + lr]);
            aq[kk][1] = __float_as_uint(qb[8 * KSTR + kk * 8 + lr]);
            aq[kk][2] = __float_as_uint(qb[kk * 8 + lr + 4]);
            aq[kk][3] = __float_as_uint(qb[8 * KSTR + kk * 8 + lr + 4]);
        }
    }
    __syncthreads();    // Q consumed; smem reusable for K/V stages

    const uint32_t sb = smem_u32(sm);
    auto load_kv = [&](int stg, int kt) {
        uint32_t ks = sb + (uint32_t)stg * (KVSTG * 4);
        uint32_t vs = ks + 32 * KSTR * 4;
#pragma unroll
        for (int l = 0; l < 2; l++) {
            int f  = tid + l * 256;       // 0..511
            int r  = f >> 4;              // 0..31
            int cc = (f & 15) << 2;       // 0..60
            const float* src = base + 64 + (size_t)(kt * 32 + r) * rs + cc;
            uint32_t doff = (uint32_t)(r * KSTR + cc) * 4;
            CP_ASYNC16(ks + doff, src);
            CP_ASYNC16(vs + doff, src + 64);
        }
    };

    float o[8][4];
#pragma unroll
    for (int ni = 0; ni < 8; ni++)
#pragma unroll
        for (int j = 0; j < 4; j++) o[ni][j] = 0.f;
    float m0 = -INFINITY, m1 = -INFINITY, l0 = 0.f, l1 = 0.f;

    load_kv(0, 0);
    CP_COMMIT();

    const int NT = SEQ / 32;
    for (int kt = 0; kt < NT; kt++) {
        const int buf = kt & 1;
        CP_WAIT0();               // stage kt landed
        __syncthreads();          // everyone done computing on buf^1
        if (kt + 1 < NT) {
            load_kv(buf ^ 1, kt + 1);
            CP_COMMIT();
        }

        const float* Ks = sm + buf * KVSTG;
        const float* Vs = Ks + 32 * KSTR;

        // ---- S = Q K^T ----
        float s[4][4];
#pragma unroll
        for (int ni = 0; ni < 4; ni++)
#pragma unroll
            for (int j = 0; j < 4; j++) s[ni][j] = 0.f;

#pragma unroll
        for (int kk = 0; kk < 8; kk++) {
            uint32_t bk[4][2];
#pragma unroll
            for (int ni = 0; ni < 4; ni++) {
                const float* kb = Ks + (ni * 8 + lq) * KSTR + kk * 8 + lr;
                bk[ni][0] = __float_as_uint(kb[0]);
                bk[ni][1] = __float_as_uint(kb[4]);
            }
#pragma unroll
            for (int ni = 0; ni < 4; ni++)
                MMA_TF32(s[ni][0], s[ni][1], s[ni][2], s[ni][3],
                         aq[kk][0], aq[kk][1], aq[kk][2], aq[kk][3],
                         bk[ni][0], bk[ni][1]);
        }

        // ---- online softmax on fragments (rows lq, lq+8) ----
        float mx0 = -INFINITY, mx1 = -INFINITY;
#pragma unroll
        for (int ni = 0; ni < 4; ni++) {
            mx0 = fmaxf(mx0, fmaxf(s[ni][0], s[ni][1]));
            mx1 = fmaxf(mx1, fmaxf(s[ni][2], s[ni][3]));
        }
        mx0 = fmaxf(mx0, __shfl_xor_sync(0xffffffffu, mx0, 1));
        mx0 = fmaxf(mx0, __shfl_xor_sync(0xffffffffu, mx0, 2));
        mx1 = fmaxf(mx1, __shfl_xor_sync(0xffffffffu, mx1, 1));
        mx1 = fmaxf(mx1, __shfl_xor_sync(0xffffffffu, mx1, 2));

        float mn0 = fmaxf(m0, mx0);
        float mn1 = fmaxf(m1, mx1);
        float corr0 = __expf(m0 - mn0);
        float corr1 = __expf(m1 - mn1);
        m0 = mn0; m1 = mn1;

        float sum0 = 0.f, sum1 = 0.f;
#pragma unroll
        for (int ni = 0; ni < 4; ni++) {
            float p0 = __expf(s[ni][0] - m0);
            float p1 = __expf(s[ni][1] - m0);
            float p2 = __expf(s[ni][2] - m1);
            float p3 = __expf(s[ni][3] - m1);
            sum0 += p0 + p1;
            sum1 += p2 + p3;
            // store back tf32-rounded P into s (shfl source regs)
            s[ni][0] = cvt_tf32(p0); s[ni][1] = cvt_tf32(p1);
            s[ni][2] = cvt_tf32(p2); s[ni][3] = cvt_tf32(p3);
        }
        sum0 += __shfl_xor_sync(0xffffffffu, sum0, 1);
        sum0 += __shfl_xor_sync(0xffffffffu, sum0, 2);
        sum1 += __shfl_xor_sync(0xffffffffu, sum1, 1);
        sum1 += __shfl_xor_sync(0xffffffffu, sum1, 2);
        l0 = l0 * corr0 + sum0;
        l1 = l1 * corr1 + sum1;

#pragma unroll
        for (int ni = 0; ni < 8; ni++) {
            o[ni][0] *= corr0; o[ni][1] *= corr0;
            o[ni][2] *= corr1; o[ni][3] *= corr1;
        }

        // ---- O += P V, P A-fragments built by quad shfl transpose ----
        const int qbase = lane & ~3;          // 4*lq
        const int half  = lr >> 1;            // 0..1
        const int par   = lr & 1;             // slot parity
#pragma unroll
        for (int t = 0; t < 4; t++) {         // k-step: kv cols 8t..8t+7
            float v0 = __shfl_sync(0xffffffffu, s[t][0], qbase + half);
            float v1 = __shfl_sync(0xffffffffu, s[t][1], qbase + half);
            float v2 = __shfl_sync(0xffffffffu, s[t][2], qbase + half);
            float v3 = __shfl_sync(0xffffffffu, s[t][3], qbase + half);
            float w0 = __shfl_sync(0xffffffffu, s[t][0], qbase + 2 + half);
            float w1 = __shfl_sync(0xffffffffu, s[t][1], qbase + 2 + half);
            float w2 = __shfl_sync(0xffffffffu, s[t][2], qbase + 2 + half);
            float w3 = __shfl_sync(0xffffffffu, s[t][3], qbase + 2 + half);
            uint32_t pa0 = __float_as_uint(par ? v1 : v0);
            uint32_t pa1 = __float_as_uint(par ? v3 : v2);
            uint32_t pa2 = __float_as_uint(par ? w1 : w0);
            uint32_t pa3 = __float_as_uint(par ? w3 : w2);
#pragma unroll
            for (int ni = 0; ni < 8; ni++) {
                uint32_t vb0 = __float_as_uint(Vs[(t * 8 + lr) * KSTR + ni * 8 + lq]);
                uint32_t vb1 = __float_as_uint(Vs[(t * 8 + lr + 4) * KSTR + ni * 8 + lq]);
                MMA_TF32(o[ni][0], o[ni][1], o[ni][2], o[ni][3],
                         pa0, pa1, pa2, pa3, vb0, vb1);
            }
        }
    }

    // ---- finalize + write (tf32-rounded for GEMM3) ----
    float inv0 = 1.f / l0;
    float inv1 = 1.f / l1;
    int gq = qt * 128 + w * 16 + lq;
    float* orow0 = att + (size_t)(b * SEQ + gq) * EMBED + h * HD;
    float* orow1 = orow0 + (size_t)8 * EMBED;
#pragma unroll
    for (int ni = 0; ni < 8; ni++) {
        int col = ni * 8 + 2 * lr;
        *reinterpret_cast<float2*>(orow0 + col) =
            make_float2(cvt_tf32(o[ni][0] * inv0), cvt_tf32(o[ni][1] * inv0));
        *reinterpret_cast<float2*>(orow1 + col) =
            make_float2(cvt_tf32(o[ni][2] * inv1), cvt_tf32(o[ni][3] * inv1));
    }
}

// ---------------------------------------------------------------------------
extern "C" void kernel_launch(void* const* d_in, const int* in_sizes, int n_in,
                              void* d_out, int out_size)
{
    (void)in_sizes; (void)n_in; (void)out_size;
    const float* x     = (const float*)d_in[0];
    const float* qkv_w = (const float*)d_in[1];
    const float* qkv_b = (const float*)d_in[2];
    const float* out_w = (const float*)d_in[3];
    const float* out_b = (const float*)d_in[4];
    float* out = (float*)d_out;

    float *qkv_buf, *att_buf;
    cudaGetSymbolAddress((void**)&qkv_buf, g_qkv);
    cudaGetSymbolAddress((void**)&att_buf, g_att);

    // 1) qkv = x @ qkv_w^T + qkv_b    [8192, 3072], tf32-rounded output
    gemm_mma_kernel<<<dim3(QKVCOLS / 128, ROWS / 128), 256>>>(
        x, qkv_w, qkv_b, qkv_buf, ROWS, QKVCOLS, EMBED, 1);

    // 2) attention -> att [8192, 1024], tf32-rounded output
    attn_mma_kernel<<<dim3(SEQ / 128, BATCH * NHEADS), 256>>>(qkv_buf, att_buf);

    // 3) out = att @ out_w^T + out_b  [8192, 1024]
    gemm_mma_kernel<<<dim3(EMBED / 128, ROWS / 128), 256>>>(
        att_buf, out_w, out_b, out, ROWS, EMBED, EMBED, 0);
}

// round 13
// speedup vs baseline: 1.7533x; 1.4683x over previous
#include <cuda_runtime.h>
#include <cuda_fp16.h>
#include <math.h>
#include <stdint.h>

#define EMBED   1024
#define NHEADS  16
#define HD      64
#define BATCH   4
#define SEQ     2048
#define ROWS    (BATCH * SEQ)          // 8192
#define QKVCOLS (3 * EMBED)            // 3072

// Scratch (allocation-free rule: device globals)
__device__ __half g_qkv[(size_t)ROWS * QKVCOLS];  // fp16 qkv, q pre-scaled by 0.125
__device__ __half g_att[(size_t)ROWS * EMBED];    // fp16 attention output

__device__ __forceinline__ uint32_t f22h2(float lo, float hi) {
    __half2 h = __floats2half2_rn(lo, hi);
    return *reinterpret_cast<uint32_t*>(&h);
}

// D += A(16x16,row) * B(16x8,col)  f16 -> f32
#define MMA_F16(c0,c1,c2,c3,a0,a1,a2,a3,b0,b1) \
    asm volatile("mma.sync.aligned.m16n8k16.row.col.f32.f16.f16.f32 " \
                 "{%0,%1,%2,%3}, {%4,%5,%6,%7}, {%8,%9}, {%0,%1,%2,%3};" \
                 : "+f"(c0), "+f"(c1), "+f"(c2), "+f"(c3) \
                 : "r"(a0), "r"(a1), "r"(a2), "r"(a3), "r"(b0), "r"(b1))

// ============================================================================
// fp16 mma.sync GEMM: C = A @ W^T + bias. CTA 128x128, K-tile 32 (2 k16 steps),
// 8 warps 4(M)x2(N), warp tile 32x64. SMEM rows padded to 40 halves.
// MODE 0: A fp32, C fp16 (q-cols scaled 0.125)   [GEMM1: x -> qkv]
// MODE 1: A fp16, C fp32                          [GEMM3: att -> out]
// ============================================================================
#define GKT 32
#define HSTR 40

template<int MODE>
__global__ __launch_bounds__(256) void gemm_f16_kernel(
    const void* __restrict__ Av, const float* __restrict__ W,
    const float* __restrict__ bias, void* __restrict__ Cv,
    int M, int N, int K)
{
    __shared__ __half As[128 * HSTR];
    __shared__ __half Bs[128 * HSTR];

    const int tid    = threadIdx.x;
    const int lane   = tid & 31;
    const int wid    = tid >> 5;
    const int warp_m = wid & 3;
    const int warp_n = wid >> 2;
    const int row0   = blockIdx.y * 128;
    const int col0   = blockIdx.x * 128;

    const int lq = lane >> 2;
    const int lr = lane & 3;

    float c[2][8][4];
#pragma unroll
    for (int mi = 0; mi < 2; mi++)
#pragma unroll
        for (int ni = 0; ni < 8; ni++)
#pragma unroll
            for (int j = 0; j < 4; j++) c[mi][ni][j] = 0.f;

    const int NKT = K / GKT;
    for (int kt = 0; kt < NKT; kt++) {
        if (kt > 0) __syncthreads();
        const int k0 = kt * GKT;

        // ---- load A tile ----
        if (MODE == 0) {
            const float* A = (const float*)Av;
#pragma unroll
            for (int l = 0; l < 4; l++) {
                int f  = tid + l * 256;          // 0..1023
                int r  = f >> 3;
                int c4 = (f & 7) << 2;
                float4 v = *reinterpret_cast<const float4*>(A + (size_t)(row0 + r) * K + k0 + c4);
                uint2 h;
                h.x = f22h2(v.x, v.y);
                h.y = f22h2(v.z, v.w);
                *reinterpret_cast<uint2*>(As + r * HSTR + c4) = h;
            }
        } else {
            const __half* A = (const __half*)Av;
#pragma unroll
            for (int l = 0; l < 2; l++) {
                int f  = tid + l * 256;          // 0..511
                int r  = f >> 2;
                int ch = (f & 3) << 3;           // 0,8,16,24 halves
                uint4 v = *reinterpret_cast<const uint4*>(A + (size_t)(row0 + r) * K + k0 + ch);
                *reinterpret_cast<uint4*>(As + r * HSTR + ch) = v;
            }
        }
        // ---- load W tile (always fp32 -> fp16) ----
#pragma unroll
        for (int l = 0; l < 4; l++) {
            int f  = tid + l * 256;
            int r  = f >> 3;
            int c4 = (f & 7) << 2;
            float4 v = *reinterpret_cast<const float4*>(W + (size_t)(col0 + r) * K + k0 + c4);
            uint2 h;
            h.x = f22h2(v.x, v.y);
            h.y = f22h2(v.z, v.w);
            *reinterpret_cast<uint2*>(Bs + r * HSTR + c4) = h;
        }
        __syncthreads();

#pragma unroll
        for (int kk = 0; kk < 2; kk++) {        // two k16 steps
            const int kb = kk * 16;
            uint32_t a[2][4];
#pragma unroll
            for (int mi = 0; mi < 2; mi++) {
                const __half* ab = As + (warp_m * 32 + mi * 16 + lq) * HSTR + kb + 2 * lr;
                a[mi][0] = *reinterpret_cast<const uint32_t*>(ab);
                a[mi][1] = *reinterpret_cast<const uint32_t*>(ab + 8 * HSTR);
                a[mi][2] = *reinterpret_cast<const uint32_t*>(ab + 8);
                a[mi][3] = *reinterpret_cast<const uint32_t*>(ab + 8 * HSTR + 8);
            }
            uint32_t b[8][2];
#pragma unroll
            for (int ni = 0; ni < 8; ni++) {
                const __half* bb = Bs + (warp_n * 64 + ni * 8 + lq) * HSTR + kb + 2 * lr;
                b[ni][0] = *reinterpret_cast<const uint32_t*>(bb);
                b[ni][1] = *reinterpret_cast<const uint32_t*>(bb + 8);
            }
#pragma unroll
            for (int mi = 0; mi < 2; mi++)
#pragma unroll
                for (int ni = 0; ni < 8; ni++)
                    MMA_F16(c[mi][ni][0], c[mi][ni][1], c[mi][ni][2], c[mi][ni][3],
                            a[mi][0], a[mi][1], a[mi][2], a[mi][3],
                            b[ni][0], b[ni][1]);
        }
    }

    // ---- epilogue ----
#pragma unroll
    for (int mi = 0; mi < 2; mi++) {
        int rg = row0 + warp_m * 32 + mi * 16 + lq;
#pragma unroll
        for (int ni = 0; ni < 8; ni++) {
            int cg = col0 + warp_n * 64 + ni * 8 + 2 * lr;
            float bx = bias[cg], by = bias[cg + 1];
            float v00 = c[mi][ni][0] + bx, v01 = c[mi][ni][1] + by;
            float v10 = c[mi][ni][2] + bx, v11 = c[mi][ni][3] + by;
            if (MODE == 0) {
                // pre-scale q columns by 1/sqrt(hd) = 0.125 (exact)
                if ((cg % 192) < 64) {
                    v00 *= 0.125f; v01 *= 0.125f; v10 *= 0.125f; v11 *= 0.125f;
                }
                __half* C = (__half*)Cv;
                *reinterpret_cast<uint32_t*>(C + (size_t)rg * N + cg)       = f22h2(v00, v01);
                *reinterpret_cast<uint32_t*>(C + (size_t)(rg + 8) * N + cg) = f22h2(v10, v11);
            } else {
                float* C = (float*)Cv;
                *reinterpret_cast<float2*>(C + (size_t)rg * N + cg)       = make_float2(v00, v01);
                *reinterpret_cast<float2*>(C + (size_t)(rg + 8) * N + cg) = make_float2(v10, v11);
            }
        }
    }
}

// ============================================================================
// fp16 tensor-core flash attention. CTA: 8 warps, 128 q-rows of one (b,h),
// kv-tiles of 32. S C-frag == P A-frag (fp16 trick): P never leaves registers.
// Smem: Q staging [128][72] halves, aliased by K [32][72] + V^T [64][34].
// ============================================================================
#define QSTR 72
#define VSTR 34

__global__ __launch_bounds__(256) void attn_f16_kernel(const __half* __restrict__ qkv,
                                                       __half* __restrict__ att)
{
    __shared__ __half smh[128 * QSTR];      // 18432 B

    const int tid  = threadIdx.x;
    const int lane = tid & 31;
    const int w    = tid >> 5;
    const int lq   = lane >> 2;
    const int lr   = lane & 3;

    const int qt = blockIdx.x;
    const int bh = blockIdx.y;
    const int b  = bh >> 4;
    const int h  = bh & 15;

    const size_t rs = QKVCOLS;
    const __half* base = qkv + (size_t)b * SEQ * rs + h * (3 * HD);

    // ---- stage Q tile [128][64] halves (already scaled by GEMM1) ----
#pragma unroll
    for (int l = 0; l < 4; l++) {
        int f  = tid + l * 256;              // 0..1023
        int r  = f >> 3;
        int ch = (f & 7) << 3;               // 0..56
        uint4 v = *reinterpret_cast<const uint4*>(base + (size_t)(qt * 128 + r) * rs + ch);
        *reinterpret_cast<uint4*>(smh + r * QSTR + ch) = v;
    }
    __syncthreads();

    // ---- persistent Q fragments: 4 k16-steps x 4 regs ----
    uint32_t aq[4][4];
    {
        const __half* qb = smh + (w * 16 + lq) * QSTR + 2 * lr;
#pragma unroll
        for (int kk = 0; kk < 4; kk++) {
            aq[kk][0] = *reinterpret_cast<const uint32_t*>(qb + kk * 16);
            aq[kk][1] = *reinterpret_cast<const uint32_t*>(qb + 8 * QSTR + kk * 16);
            aq[kk][2] = *reinterpret_cast<const uint32_t*>(qb + kk * 16 + 8);
            aq[kk][3] = *reinterpret_cast<const uint32_t*>(qb + 8 * QSTR + kk * 16 + 8);
        }
    }
    __syncthreads();    // Q consumed; smem reusable

    __half* Ks = smh;                        // [32][72]
    __half* Vt = smh + 32 * QSTR;            // [64][34] transposed V

    float o[8][4];
#pragma unroll
    for (int ni = 0; ni < 8; ni++)
#pragma unroll
        for (int j = 0; j < 4; j++) o[ni][j] = 0.f;
    float m0 = -INFINITY, m1 = -INFINITY, l0 = 0.f, l1 = 0.f;

    for (int kt = 0; kt < SEQ / 32; kt++) {
        if (kt > 0) __syncthreads();
        // K tile: 32 rows x 8 chunks of 8 halves = 256 chunks (1/thread)
        {
            int r  = tid >> 3;
            int ch = (tid & 7) << 3;
            uint4 v = *reinterpret_cast<const uint4*>(base + 64 + (size_t)(kt * 32 + r) * rs + ch);
            *reinterpret_cast<uint4*>(Ks + r * QSTR + ch) = v;
        }
        // V tile transposed: 32 rows x 16 chunks of 4 halves = 512 (2/thread)
#pragma unroll
        for (int l = 0; l < 2; l++) {
            int f  = tid + l * 256;
            int r  = f >> 4;                 // kv row 0..31
            int ch = (f & 15) << 2;          // hd col 0..60
            uint2 v = *reinterpret_cast<const uint2*>(base + 128 + (size_t)(kt * 32 + r) * rs + ch);
            const __half* hp = reinterpret_cast<const __half*>(&v);
            Vt[(ch + 0) * VSTR + r] = hp[0];
            Vt[(ch + 1) * VSTR + r] = hp[1];
            Vt[(ch + 2) * VSTR + r] = hp[2];
            Vt[(ch + 3) * VSTR + r] = hp[3];
        }
        __syncthreads();

        // ---- S = Q K^T : 4 k16-steps x 4 n-subtiles ----
        float s[4][4];
#pragma unroll
        for (int ni = 0; ni < 4; ni++)
#pragma unroll
            for (int j = 0; j < 4; j++) s[ni][j] = 0.f;

#pragma unroll
        for (int kk = 0; kk < 4; kk++) {
            uint32_t bk[4][2];
#pragma unroll
            for (int ni = 0; ni < 4; ni++) {
                const __half* kb = Ks + (ni * 8 + lq) * QSTR + kk * 16 + 2 * lr;
                bk[ni][0] = *reinterpret_cast<const uint32_t*>(kb);
                bk[ni][1] = *reinterpret_cast<const uint32_t*>(kb + 8);
            }
#pragma unroll
            for (int ni = 0; ni < 4; ni++)
                MMA_F16(s[ni][0], s[ni][1], s[ni][2], s[ni][3],
                        aq[kk][0], aq[kk][1], aq[kk][2], aq[kk][3],
                        bk[ni][0], bk[ni][1]);
        }

        // ---- online softmax on fragments (rows lq, lq+8) ----
        float mx0 = -INFINITY, mx1 = -INFINITY;
#pragma unroll
        for (int ni = 0; ni < 4; ni++) {
            mx0 = fmaxf(mx0, fmaxf(s[ni][0], s[ni][1]));
            mx1 = fmaxf(mx1, fmaxf(s[ni][2], s[ni][3]));
        }
        mx0 = fmaxf(mx0, __shfl_xor_sync(0xffffffffu, mx0, 1));
        mx0 = fmaxf(mx0, __shfl_xor_sync(0xffffffffu, mx0, 2));
        mx1 = fmaxf(mx1, __shfl_xor_sync(0xffffffffu, mx1, 1));
        mx1 = fmaxf(mx1, __shfl_xor_sync(0xffffffffu, mx1, 2));

        float mn0 = fmaxf(m0, mx0);
        float mn1 = fmaxf(m1, mx1);
        float corr0 = __expf(m0 - mn0);
        float corr1 = __expf(m1 - mn1);
        m0 = mn0; m1 = mn1;

        float sum0 = 0.f, sum1 = 0.f;
#pragma unroll
        for (int ni = 0; ni < 4; ni++) {
            s[ni][0] = __expf(s[ni][0] - m0);
            s[ni][1] = __expf(s[ni][1] - m0);
            s[ni][2] = __expf(s[ni][2] - m1);
            s[ni][3] = __expf(s[ni][3] - m1);
            sum0 += s[ni][0] + s[ni][1];
            sum1 += s[ni][2] + s[ni][3];
        }
        sum0 += __shfl_xor_sync(0xffffffffu, sum0, 1);
        sum0 += __shfl_xor_sync(0xffffffffu, sum0, 2);
        sum1 += __shfl_xor_sync(0xffffffffu, sum1, 1);
        sum1 += __shfl_xor_sync(0xffffffffu, sum1, 2);
        l0 = l0 * corr0 + sum0;
        l1 = l1 * corr1 + sum1;

#pragma unroll
        for (int ni = 0; ni < 8; ni++) {
            o[ni][0] *= corr0; o[ni][1] *= corr0;
            o[ni][2] *= corr1; o[ni][3] *= corr1;
        }

        // ---- O += P V : P A-frags are this thread's own S regs (fp16 trick)
#pragma unroll
        for (int t = 0; t < 2; t++) {        // k16-step over kv
            uint32_t pa0 = f22h2(s[2 * t][0],     s[2 * t][1]);
            uint32_t pa1 = f22h2(s[2 * t][2],     s[2 * t][3]);
            uint32_t pa2 = f22h2(s[2 * t + 1][0], s[2 * t + 1][1]);
            uint32_t pa3 = f22h2(s[2 * t + 1][2], s[2 * t + 1][3]);
#pragma unroll
            for (int ni = 0; ni < 8; ni++) {
                const __half* vb = Vt + (ni * 8 + lq) * VSTR + t * 16 + 2 * lr;
                uint32_t b0 = *reinterpret_cast<const uint32_t*>(vb);
                uint32_t b1 = *reinterpret_cast<const uint32_t*>(vb + 8);
                MMA_F16(o[ni][0], o[ni][1], o[ni][2], o[ni][3],
                        pa0, pa1, pa2, pa3, b0, b1);
            }
        }
    }

    // ---- finalize + write att (fp16) ----
    float inv0 = 1.f / l0;
    float inv1 = 1.f / l1;
    int gq = qt * 128 + w * 16 + lq;
    __half* orow0 = att + (size_t)(b * SEQ + gq) * EMBED + h * HD;
    __half* orow1 = orow0 + (size_t)8 * EMBED;
#pragma unroll
    for (int ni = 0; ni < 8; ni++) {
        int col = ni * 8 + 2 * lr;
        *reinterpret_cast<uint32_t*>(orow0 + col) = f22h2(o[ni][0] * inv0, o[ni][1] * inv0);
        *reinterpret_cast<uint32_t*>(orow1 + col) = f22h2(o[ni][2] * inv1, o[ni][3] * inv1);
    }
}

// ---------------------------------------------------------------------------
extern "C" void kernel_launch(void* const* d_in, const int* in_sizes, int n_in,
                              void* d_out, int out_size)
{
    (void)in_sizes; (void)n_in; (void)out_size;
    const float* x     = (const float*)d_in[0];
    const float* qkv_w = (const float*)d_in[1];
    const float* qkv_b = (const float*)d_in[2];
    const float* out_w = (const float*)d_in[3];
    const float* out_b = (const float*)d_in[4];
    float* out = (float*)d_out;

    __half *qkv_buf, *att_buf;
    cudaGetSymbolAddress((void**)&qkv_buf, g_qkv);
    cudaGetSymbolAddress((void**)&att_buf, g_att);

    // 1) qkv = x @ qkv_w^T + qkv_b  -> fp16, q cols pre-scaled
    gemm_f16_kernel<0><<<dim3(QKVCOLS / 128, ROWS / 128), 256>>>(
        x, qkv_w, qkv_b, qkv_buf, ROWS, QKVCOLS, EMBED);

    // 2) attention -> att (fp16)
    attn_f16_kernel<<<dim3(SEQ / 128, BATCH * NHEADS), 256>>>(qkv_buf, att_buf);

    // 3) out = att @ out_w^T + out_b (fp32)
    gemm_f16_kernel<1><<<dim3(EMBED / 128, ROWS / 128), 256>>>(
        att_buf, out_w, out_b, out, ROWS, EMBED, EMBED);
}

// round 15
// speedup vs baseline: 2.4335x; 1.3880x over previous
#include <cuda_runtime.h>
#include <cuda_fp16.h>
#include <math.h>
#include <stdint.h>

#define EMBED   1024
#define NHEADS  16
#define HD      64
#define BATCH   4
#define SEQ     2048
#define ROWS    (BATCH * SEQ)          // 8192
#define QKVCOLS (3 * EMBED)            // 3072

// Scratch (allocation-free rule: device globals)
__device__ __half g_qkv[(size_t)ROWS * QKVCOLS];   // fp16 qkv, q pre-scaled
__device__ __half g_att[(size_t)ROWS * EMBED];     // fp16 attention output
__device__ __half g_xh[(size_t)ROWS * EMBED];      // fp16 x
__device__ __half g_wqkvh[(size_t)QKVCOLS * EMBED];// fp16 qkv_w
__device__ __half g_wouth[(size_t)EMBED * EMBED];  // fp16 out_w

__device__ __forceinline__ uint32_t f22h2(float lo, float hi) {
    __half2 h = __floats2half2_rn(lo, hi);
    return *reinterpret_cast<uint32_t*>(&h);
}
__device__ __forceinline__ uint32_t smem_u32(const void* p) {
    uint32_t a;
    asm("{ .reg .u64 t; cvta.to.shared.u64 t, %1; cvt.u32.u64 %0, t; }" : "=r"(a) : "l"(p));
    return a;
}

#define CP_ASYNC16(dst, src) \
    asm volatile("cp.async.cg.shared.global [%0], [%1], 16;" :: "r"(dst), "l"(src))
#define CP_COMMIT() asm volatile("cp.async.commit_group;" ::: "memory")
#define CP_WAIT0()  asm volatile("cp.async.wait_group 0;" ::: "memory")

#define MMA_F16(c0,c1,c2,c3,a0,a1,a2,a3,b0,b1) \
    asm volatile("mma.sync.aligned.m16n8k16.row.col.f32.f16.f16.f32 " \
                 "{%0,%1,%2,%3}, {%4,%5,%6,%7}, {%8,%9}, {%0,%1,%2,%3};" \
                 : "+f"(c0), "+f"(c1), "+f"(c2), "+f"(c3) \
                 : "r"(a0), "r"(a1), "r"(a2), "r"(a3), "r"(b0), "r"(b1))

#define LDSM_X4(r0,r1,r2,r3,addr) \
    asm volatile("ldmatrix.sync.aligned.m8n8.x4.shared.b16 {%0,%1,%2,%3}, [%4];" \
                 : "=r"(r0), "=r"(r1), "=r"(r2), "=r"(r3) : "r"(addr))
#define LDSM_X4_T(r0,r1,r2,r3,addr) \
    asm volatile("ldmatrix.sync.aligned.m8n8.x4.trans.shared.b16 {%0,%1,%2,%3}, [%4];" \
                 : "=r"(r0), "=r"(r1), "=r"(r2), "=r"(r3) : "r"(addr))

// ============================================================================
// fp32 -> fp16 pre-conversion (grid-stride, float4 -> 4 halves)
// ============================================================================
__global__ __launch_bounds__(256) void cvt_f16_kernel(
    const float* __restrict__ src, __half* __restrict__ dst, int n4)
{
    int i = blockIdx.x * blockDim.x + threadIdx.x;
    int stride = gridDim.x * blockDim.x;
    for (; i < n4; i += stride) {
        float4 v = reinterpret_cast<const float4*>(src)[i];
        uint2 h;
        h.x = f22h2(v.x, v.y);
        h.y = f22h2(v.z, v.w);
        reinterpret_cast<uint2*>(dst)[i] = h;
    }
}

// ============================================================================
// fp16 mma.sync GEMM, cp.async 2-stage + ldmatrix. C = A @ W^T + bias.
// CTA 128x128, K-tile 32 halves (2 k16 steps), 8 warps 4(M)x2(N).
// Stage: A 128x40 + B 128x40 halves; 2 stages = 40960 B static.
// Loader: 128 rows x 4 chunks (32 halves) x 2 matrices = 1024 cp.async / 256thr
// MODE 0: C fp16 with q-col scaling (GEMM1). MODE 1: C fp32 (GEMM3).
// ============================================================================
#define GKT 32
#define HSTR 40                         // halves; 80 B rows (16B aligned)
#define GSTGH (128 * HSTR)              // halves per matrix per stage

template<int MODE>
__global__ __launch_bounds__(256) void gemm_f16_kernel(
    const __half* __restrict__ A, const __half* __restrict__ W,
    const float* __restrict__ bias, void* __restrict__ Cv,
    int M, int N, int K)
{
    __shared__ __half sA[2][GSTGH];
    __shared__ __half sB[2][GSTGH];

    const int tid    = threadIdx.x;
    const int lane   = tid & 31;
    const int wid    = tid >> 5;
    const int warp_m = wid & 3;
    const int warp_n = wid >> 2;
    const int row0   = blockIdx.y * 128;
    const int col0   = blockIdx.x * 128;

    const int lq = lane >> 2;
    const int lr = lane & 3;

    // ldmatrix lane-role offsets
    const int a_r = (lane & 7) + ((lane >> 3) & 1) * 8;   // row within 16
    const int a_c = (lane >> 4) * 8;                      // col halves {0,8}
    const int b_r = (lane & 7) + (lane >> 4) * 8;         // n-row within 16
    const int b_c = ((lane >> 3) & 1) * 8;                // col halves {0,8}

    const uint32_t sAu = smem_u32(&sA[0][0]);
    const uint32_t sBu = smem_u32(&sB[0][0]);

    float c[2][8][4];
#pragma unroll
    for (int mi = 0; mi < 2; mi++)
#pragma unroll
        for (int ni = 0; ni < 8; ni++)
#pragma unroll
            for (int j = 0; j < 4; j++) c[mi][ni][j] = 0.f;

    // stage loader: 128 rows x 4 chunks of 8 halves x 2 matrices
    auto load_stage = [&](int stg, int k0) {
        uint32_t as = sAu + (uint32_t)stg * (GSTGH * 2);
        uint32_t bs = sBu + (uint32_t)stg * (GSTGH * 2);
#pragma unroll
        for (int l = 0; l < 2; l++) {
            int f  = tid + l * 256;       // 0..511
            int r  = f >> 2;              // 0..127
            int ch = (f & 3) << 3;        // 0,8,16,24 halves
            uint32_t doff = (uint32_t)(r * HSTR + ch) * 2;
            CP_ASYNC16(as + doff, A + (size_t)(row0 + r) * K + k0 + ch);
            CP_ASYNC16(bs + doff, W + (size_t)(col0 + r) * K + k0 + ch);
        }
    };

    const int NKT = K / GKT;
    load_stage(0, 0);
    CP_COMMIT();

    for (int kt = 0; kt < NKT; kt++) {
        const int buf = kt & 1;
        CP_WAIT0();
        __syncthreads();
        if (kt + 1 < NKT) {
            load_stage(buf ^ 1, (kt + 1) * GKT);
            CP_COMMIT();
        }

        const uint32_t aBase = sAu + (uint32_t)buf * (GSTGH * 2);
        const uint32_t bBase = sBu + (uint32_t)buf * (GSTGH * 2);

#pragma unroll
        for (int kk = 0; kk < 2; kk++) {
            const int kb = kk * 16;
            uint32_t a[2][4];
#pragma unroll
            for (int mi = 0; mi < 2; mi++) {
                uint32_t addr = aBase +
                    (uint32_t)((warp_m * 32 + mi * 16 + a_r) * HSTR + kb + a_c) * 2;
                LDSM_X4(a[mi][0], a[mi][1], a[mi][2], a[mi][3], addr);
            }
            uint32_t b[8][2];
#pragma unroll
            for (int ni = 0; ni < 8; ni += 2) {
                uint32_t addr = bBase +
                    (uint32_t)((warp_n * 64 + ni * 8 + b_r) * HSTR + kb + b_c) * 2;
                LDSM_X4(b[ni][0], b[ni][1], b[ni + 1][0], b[ni + 1][1], addr);
            }
#pragma unroll
            for (int mi = 0; mi < 2; mi++)
#pragma unroll
                for (int ni = 0; ni < 8; ni++)
                    MMA_F16(c[mi][ni][0], c[mi][ni][1], c[mi][ni][2], c[mi][ni][3],
                            a[mi][0], a[mi][1], a[mi][2], a[mi][3],
                            b[ni][0], b[ni][1]);
        }
    }

    // ---- epilogue ----
#pragma unroll
    for (int mi = 0; mi < 2; mi++) {
        int rg = row0 + warp_m * 32 + mi * 16 + lq;
#pragma unroll
        for (int ni = 0; ni < 8; ni++) {
            int cg = col0 + warp_n * 64 + ni * 8 + 2 * lr;
            float bx = bias[cg], by = bias[cg + 1];
            float v00 = c[mi][ni][0] + bx, v01 = c[mi][ni][1] + by;
            float v10 = c[mi][ni][2] + bx, v11 = c[mi][ni][3] + by;
            if (MODE == 0) {
                if ((cg % 192) < 64) {     // q columns: pre-scale by 0.125
                    v00 *= 0.125f; v01 *= 0.125f; v10 *= 0.125f; v11 *= 0.125f;
                }
                __half* C = (__half*)Cv;
                *reinterpret_cast<uint32_t*>(C + (size_t)rg * N + cg)       = f22h2(v00, v01);
                *reinterpret_cast<uint32_t*>(C + (size_t)(rg + 8) * N + cg) = f22h2(v10, v11);
            } else {
                float* C = (float*)Cv;
                *reinterpret_cast<float2*>(C + (size_t)rg * N + cg)       = make_float2(v00, v01);
                *reinterpret_cast<float2*>(C + (size_t)(rg + 8) * N + cg) = make_float2(v10, v11);
            }
        }
    }
}

// ============================================================================
// fp16 flash attention, cp.async 2-stage K/V + ldmatrix (V via .trans).
// CTA: 8 warps, 128 q-rows of one (b,h), kv-tiles of 32.
// Stage: K [32][72] + V [32][72] halves = 9216 B; 2 stages = 18432 B static.
// Q staging [128][72] aliases the stage region (consumed before preload).
// ============================================================================
#define QSTR 72
#define KVSTGH (2 * 32 * QSTR)          // halves per stage = 4608

__global__ __launch_bounds__(256) void attn_f16_kernel(const __half* __restrict__ qkv,
                                                       __half* __restrict__ att)
{
    __shared__ __half smh[2 * KVSTGH];   // 18432 B

    const int tid  = threadIdx.x;
    const int lane = tid & 31;
    const int w    = tid >> 5;
    const int lq   = lane >> 2;
    const int lr   = lane & 3;

    const int qt = blockIdx.x;
    const int bh = blockIdx.y;
    const int b  = bh >> 4;
    const int h  = bh & 15;

    const size_t rs = QKVCOLS;
    const __half* base = qkv + (size_t)b * SEQ * rs + h * (3 * HD);

    // ldmatrix lane-role offsets
    const int a_r = (lane & 7) + ((lane >> 3) & 1) * 8;
    const int a_c = (lane >> 4) * 8;
    const int b_r = (lane & 7) + (lane >> 4) * 8;
    const int b_c = ((lane >> 3) & 1) * 8;

    // ---- stage Q tile [128][64] halves (pre-scaled by GEMM1) ----
#pragma unroll
    for (int l = 0; l < 4; l++) {
        int f  = tid + l * 256;
        int r  = f >> 3;
        int ch = (f & 7) << 3;
        uint4 v = *reinterpret_cast<const uint4*>(base + (size_t)(qt * 128 + r) * rs + ch);
        *reinterpret_cast<uint4*>(smh + r * QSTR + ch) = v;
    }
    __syncthreads();

    // persistent Q fragments via ldmatrix: 4 k16-steps
    uint32_t aq[4][4];
    {
        uint32_t qBase = smem_u32(smh);
#pragma unroll
        for (int kk = 0; kk < 4; kk++) {
            uint32_t addr = qBase + (uint32_t)((w * 16 + a_r) * QSTR + kk * 16 + a_c) * 2;
            LDSM_X4(aq[kk][0], aq[kk][1], aq[kk][2], aq[kk][3], addr);
        }
    }
    __syncthreads();    // Q consumed; smem reusable for K/V stages

    const uint32_t sb = smem_u32(smh);
    // stage loader: K 256 chunks + V 256 chunks over 256 threads
    auto load_kv = [&](int stg, int kt) {
        uint32_t ks = sb + (uint32_t)stg * (KVSTGH * 2);
        uint32_t vs = ks + 32 * QSTR * 2;
        int r  = tid >> 3;
        int ch = (tid & 7) << 3;
        const __half* src = base + 64 + (size_t)(kt * 32 + r) * rs + ch;
        uint32_t doff = (uint32_t)(r * QSTR + ch) * 2;
        CP_ASYNC16(ks + doff, src);
        CP_ASYNC16(vs + doff, src + 64);
    };

    float o[8][4];
#pragma unroll
    for (int ni = 0; ni < 8; ni++)
#pragma unroll
        for (int j = 0; j < 4; j++) o[ni][j] = 0.f;
    float m0 = -INFINITY, m1 = -INFINITY, l0 = 0.f, l1 = 0.f;

    load_kv(0, 0);
    CP_COMMIT();

    const int NT = SEQ / 32;
    for (int kt = 0; kt < NT; kt++) {
        const int buf = kt & 1;
        CP_WAIT0();
        __syncthreads();
        if (kt + 1 < NT) {
            load_kv(buf ^ 1, kt + 1);
            CP_COMMIT();
        }

        const uint32_t kBase = sb + (uint32_t)buf * (KVSTGH * 2);
        const uint32_t vBase = kBase + 32 * QSTR * 2;

        // ---- S = Q K^T : K-frags via ldmatrix (2 n-subtiles per x4) ----
        float s[4][4];
#pragma unroll
        for (int ni = 0; ni < 4; ni++)
#pragma unroll
            for (int j = 0; j < 4; j++) s[ni][j] = 0.f;

#pragma unroll
        for (int kk = 0; kk < 4; kk++) {
            uint32_t bk[4][2];
#pragma unroll
            for (int ni = 0; ni < 4; ni += 2) {
                uint32_t addr = kBase +
                    (uint32_t)((ni * 8 + b_r) * QSTR + kk * 16 + b_c) * 2;
                LDSM_X4(bk[ni][0], bk[ni][1], bk[ni + 1][0], bk[ni + 1][1], addr);
            }
#pragma unroll
            for (int ni = 0; ni < 4; ni++)
                MMA_F16(s[ni][0], s[ni][1], s[ni][2], s[ni][3],
                        aq[kk][0], aq[kk][1], aq[kk][2], aq[kk][3],
                        bk[ni][0], bk[ni][1]);
        }

        // ---- online softmax on fragments (rows lq, lq+8) ----
        float mx0 = -INFINITY, mx1 = -INFINITY;
#pragma unroll
        for (int ni = 0; ni < 4; ni++) {
            mx0 = fmaxf(mx0, fmaxf(s[ni][0], s[ni][1]));
            mx1 = fmaxf(mx1, fmaxf(s[ni][2], s[ni][3]));
        }
        mx0 = fmaxf(mx0, __shfl_xor_sync(0xffffffffu, mx0, 1));
        mx0 = fmaxf(mx0, __shfl_xor_sync(0xffffffffu, mx0, 2));
        mx1 = fmaxf(mx1, __shfl_xor_sync(0xffffffffu, mx1, 1));
        mx1 = fmaxf(mx1, __shfl_xor_sync(0xffffffffu, mx1, 2));

        float mn0 = fmaxf(m0, mx0);
        float mn1 = fmaxf(m1, mx1);
        float corr0 = __expf(m0 - mn0);
        float corr1 = __expf(m1 - mn1);
        m0 = mn0; m1 = mn1;

        float sum0 = 0.f, sum1 = 0.f;
#pragma unroll
        for (int ni = 0; ni < 4; ni++) {
            s[ni][0] = __expf(s[ni][0] - m0);
            s[ni][1] = __expf(s[ni][1] - m0);
            s[ni][2] = __expf(s[ni][2] - m1);
            s[ni][3] = __expf(s[ni][3] - m1);
            sum0 += s[ni][0] + s[ni][1];
            sum1 += s[ni][2] + s[ni][3];
        }
        sum0 += __shfl_xor_sync(0xffffffffu, sum0, 1);
        sum0 += __shfl_xor_sync(0xffffffffu, sum0, 2);
        sum1 += __shfl_xor_sync(0xffffffffu, sum1, 1);
        sum1 += __shfl_xor_sync(0xffffffffu, sum1, 2);
        l0 = l0 * corr0 + sum0;
        l1 = l1 * corr1 + sum1;

#pragma unroll
        for (int ni = 0; ni < 8; ni++) {
            o[ni][0] *= corr0; o[ni][1] *= corr0;
            o[ni][2] *= corr1; o[ni][3] *= corr1;
        }

        // ---- O += P V : P from own regs (fp16 trick), V via ldmatrix.trans
#pragma unroll
        for (int t = 0; t < 2; t++) {
            uint32_t pa0 = f22h2(s[2 * t][0],     s[2 * t][1]);
            uint32_t pa1 = f22h2(s[2 * t][2],     s[2 * t][3]);
            uint32_t pa2 = f22h2(s[2 * t + 1][0], s[2 * t + 1][1]);
            uint32_t pa3 = f22h2(s[2 * t + 1][2], s[2 * t + 1][3]);
            uint32_t vb[8][2];
#pragma unroll
            for (int ni = 0; ni < 8; ni += 2) {
                uint32_t addr = vBase +
                    (uint32_t)((t * 16 + a_r) * QSTR + ni * 8 + a_c) * 2;
                LDSM_X4_T(vb[ni][0], vb[ni][1], vb[ni + 1][0], vb[ni + 1][1], addr);
            }
#pragma unroll
            for (int ni = 0; ni < 8; ni++)
                MMA_F16(o[ni][0], o[ni][1], o[ni][2], o[ni][3],
                        pa0, pa1, pa2, pa3, vb[ni][0], vb[ni][1]);
        }
    }

    // ---- finalize + write att (fp16) ----
    float inv0 = 1.f / l0;
    float inv1 = 1.f / l1;
    int gq = qt * 128 + w * 16 + lq;
    __half* orow0 = att + (size_t)(b * SEQ + gq) * EMBED + h * HD;
    __half* orow1 = orow0 + (size_t)8 * EMBED;
#pragma unroll
    for (int ni = 0; ni < 8; ni++) {
        int col = ni * 8 + 2 * lr;
        *reinterpret_cast<uint32_t*>(orow0 + col) = f22h2(o[ni][0] * inv0, o[ni][1] * inv0);
        *reinterpret_cast<uint32_t*>(orow1 + col) = f22h2(o[ni][2] * inv1, o[ni][3] * inv1);
    }
}

// ---------------------------------------------------------------------------
extern "C" void kernel_launch(void* const* d_in, const int* in_sizes, int n_in,
                              void* d_out, int out_size)
{
    (void)in_sizes; (void)n_in; (void)out_size;
    const float* x     = (const float*)d_in[0];
    const float* qkv_w = (const float*)d_in[1];
    const float* qkv_b = (const float*)d_in[2];
    const float* out_w = (const float*)d_in[3];
    const float* out_b = (const float*)d_in[4];
    float* out = (float*)d_out;

    __half *qkv_buf, *att_buf, *xh, *wqkvh, *wouth;
    cudaGetSymbolAddress((void**)&qkv_buf, g_qkv);
    cudaGetSymbolAddress((void**)&att_buf, g_att);
    cudaGetSymbolAddress((void**)&xh, g_xh);
    cudaGetSymbolAddress((void**)&wqkvh, g_wqkvh);
    cudaGetSymbolAddress((void**)&wouth, g_wouth);

    // 0) pre-convert fp32 -> fp16
    cvt_f16_kernel<<<512, 256>>>(x, xh, ROWS * EMBED / 4);
    cvt_f16_kernel<<<512, 256>>>(qkv_w, wqkvh, QKVCOLS * EMBED / 4);
    cvt_f16_kernel<<<512, 256>>>(out_w, wouth, EMBED * EMBED / 4);

    // 1) qkv = x @ qkv_w^T + qkv_b  -> fp16, q cols pre-scaled
    gemm_f16_kernel<0><<<dim3(QKVCOLS / 128, ROWS / 128), 256>>>(
        xh, wqkvh, qkv_b, qkv_buf, ROWS, QKVCOLS, EMBED);

    // 2) attention -> att (fp16)
    attn_f16_kernel<<<dim3(SEQ / 128, BATCH * NHEADS), 256>>>(qkv_buf, att_buf);

    // 3) out = att @ out_w^T + out_b (fp32)
    gemm_f16_kernel<1><<<dim3(EMBED / 128, ROWS / 128), 256>>>(
        att_buf, wouth, out_b, out, ROWS, EMBED, EMBED);
}

// round 16
// speedup vs baseline: 2.4371x; 1.0015x over previous
#include <cuda_runtime.h>
#include <cuda_fp16.h>
#include <math.h>
#include <stdint.h>

#define EMBED   1024
#define NHEADS  16
#define HD      64
#define BATCH   4
#define SEQ     2048
#define ROWS    (BATCH * SEQ)          // 8192
#define QKVCOLS (3 * EMBED)            // 3072

// Scratch (allocation-free rule: device globals)
__device__ __half g_qkv[(size_t)ROWS * QKVCOLS];   // fp16 qkv, q pre-scaled
__device__ __half g_att[(size_t)ROWS * EMBED];     // fp16 attention output
__device__ __half g_xh[(size_t)ROWS * EMBED];      // fp16 x
__device__ __half g_wqkvh[(size_t)QKVCOLS * EMBED];// fp16 qkv_w
__device__ __half g_wouth[(size_t)EMBED * EMBED];  // fp16 out_w

__device__ __forceinline__ uint32_t f22h2(float lo, float hi) {
    __half2 h = __floats2half2_rn(lo, hi);
    return *reinterpret_cast<uint32_t*>(&h);
}
__device__ __forceinline__ uint32_t smem_u32(const void* p) {
    uint32_t a;
    asm("{ .reg .u64 t; cvta.to.shared.u64 t, %1; cvt.u32.u64 %0, t; }" : "=r"(a) : "l"(p));
    return a;
}

#define CP_ASYNC16(dst, src) \
    asm volatile("cp.async.cg.shared.global [%0], [%1], 16;" :: "r"(dst), "l"(src))
#define CP_COMMIT() asm volatile("cp.async.commit_group;" ::: "memory")
#define CP_WAIT0()  asm volatile("cp.async.wait_group 0;" ::: "memory")

#define MMA_F16(c0,c1,c2,c3,a0,a1,a2,a3,b0,b1) \
    asm volatile("mma.sync.aligned.m16n8k16.row.col.f32.f16.f16.f32 " \
                 "{%0,%1,%2,%3}, {%4,%5,%6,%7}, {%8,%9}, {%0,%1,%2,%3};" \
                 : "+f"(c0), "+f"(c1), "+f"(c2), "+f"(c3) \
                 : "r"(a0), "r"(a1), "r"(a2), "r"(a3), "r"(b0), "r"(b1))

#define LDSM_X4(r0,r1,r2,r3,addr) \
    asm volatile("ldmatrix.sync.aligned.m8n8.x4.shared.b16 {%0,%1,%2,%3}, [%4];" \
                 : "=r"(r0), "=r"(r1), "=r"(r2), "=r"(r3) : "r"(addr))
#define LDSM_X4_T(r0,r1,r2,r3,addr) \
    asm volatile("ldmatrix.sync.aligned.m8n8.x4.trans.shared.b16 {%0,%1,%2,%3}, [%4];" \
                 : "=r"(r0), "=r"(r1), "=r"(r2), "=r"(r3) : "r"(addr))

// ============================================================================
// fp32 -> fp16 pre-conversion (grid-stride, float4 -> 4 halves)
// ============================================================================
__global__ __launch_bounds__(256) void cvt_f16_kernel(
    const float* __restrict__ src, __half* __restrict__ dst, int n4)
{
    int i = blockIdx.x * blockDim.x + threadIdx.x;
    int stride = gridDim.x * blockDim.x;
    for (; i < n4; i += stride) {
        float4 v = reinterpret_cast<const float4*>(src)[i];
        uint2 h;
        h.x = f22h2(v.x, v.y);
        h.y = f22h2(v.z, v.w);
        reinterpret_cast<uint2*>(dst)[i] = h;
    }
}

// ============================================================================
// fp16 mma.sync GEMM, cp.async 2-stage + ldmatrix (R15-proven).
// CTA 128x128, K-tile 32 halves (2 k16 steps), 8 warps 4(M)x2(N).
// Stage: A 128x40 + B 128x40 halves; 2 stages = 40960 B static.
// MODE 0: C fp16 with q-col scaling (GEMM1). MODE 1: C fp32 (GEMM3).
// ============================================================================
#define GKT 32
#define HSTR 40
#define GSTGH (128 * HSTR)

template<int MODE>
__global__ __launch_bounds__(256) void gemm_f16_kernel(
    const __half* __restrict__ A, const __half* __restrict__ W,
    const float* __restrict__ bias, void* __restrict__ Cv,
    int M, int N, int K)
{
    __shared__ __half sA[2][GSTGH];
    __shared__ __half sB[2][GSTGH];

    const int tid    = threadIdx.x;
    const int lane   = tid & 31;
    const int wid    = tid >> 5;
    const int warp_m = wid & 3;
    const int warp_n = wid >> 2;
    const int row0   = blockIdx.y * 128;
    const int col0   = blockIdx.x * 128;

    const int lq = lane >> 2;
    const int lr = lane & 3;

    const int a_r = (lane & 7) + ((lane >> 3) & 1) * 8;
    const int a_c = (lane >> 4) * 8;
    const int b_r = (lane & 7) + (lane >> 4) * 8;
    const int b_c = ((lane >> 3) & 1) * 8;

    const uint32_t sAu = smem_u32(&sA[0][0]);
    const uint32_t sBu = smem_u32(&sB[0][0]);

    float c[2][8][4];
#pragma unroll
    for (int mi = 0; mi < 2; mi++)
#pragma unroll
        for (int ni = 0; ni < 8; ni++)
#pragma unroll
            for (int j = 0; j < 4; j++) c[mi][ni][j] = 0.f;

    auto load_stage = [&](int stg, int k0) {
        uint32_t as = sAu + (uint32_t)stg * (GSTGH * 2);
        uint32_t bs = sBu + (uint32_t)stg * (GSTGH * 2);
#pragma unroll
        for (int l = 0; l < 2; l++) {
            int f  = tid + l * 256;       // 0..511
            int r  = f >> 2;              // 0..127
            int ch = (f & 3) << 3;        // 0,8,16,24 halves
            uint32_t doff = (uint32_t)(r * HSTR + ch) * 2;
            CP_ASYNC16(as + doff, A + (size_t)(row0 + r) * K + k0 + ch);
            CP_ASYNC16(bs + doff, W + (size_t)(col0 + r) * K + k0 + ch);
        }
    };

    const int NKT = K / GKT;
    load_stage(0, 0);
    CP_COMMIT();

    for (int kt = 0; kt < NKT; kt++) {
        const int buf = kt & 1;
        CP_WAIT0();
        __syncthreads();
        if (kt + 1 < NKT) {
            load_stage(buf ^ 1, (kt + 1) * GKT);
            CP_COMMIT();
        }

        const uint32_t aBase = sAu + (uint32_t)buf * (GSTGH * 2);
        const uint32_t bBase = sBu + (uint32_t)buf * (GSTGH * 2);

#pragma unroll
        for (int kk = 0; kk < 2; kk++) {
            const int kb = kk * 16;
            uint32_t a[2][4];
#pragma unroll
            for (int mi = 0; mi < 2; mi++) {
                uint32_t addr = aBase +
                    (uint32_t)((warp_m * 32 + mi * 16 + a_r) * HSTR + kb + a_c) * 2;
                LDSM_X4(a[mi][0], a[mi][1], a[mi][2], a[mi][3], addr);
            }
            uint32_t b[8][2];
#pragma unroll
            for (int ni = 0; ni < 8; ni += 2) {
                uint32_t addr = bBase +
                    (uint32_t)((warp_n * 64 + ni * 8 + b_r) * HSTR + kb + b_c) * 2;
                LDSM_X4(b[ni][0], b[ni][1], b[ni + 1][0], b[ni + 1][1], addr);
            }
#pragma unroll
            for (int mi = 0; mi < 2; mi++)
#pragma unroll
                for (int ni = 0; ni < 8; ni++)
                    MMA_F16(c[mi][ni][0], c[mi][ni][1], c[mi][ni][2], c[mi][ni][3],
                            a[mi][0], a[mi][1], a[mi][2], a[mi][3],
                            b[ni][0], b[ni][1]);
        }
    }

#pragma unroll
    for (int mi = 0; mi < 2; mi++) {
        int rg = row0 + warp_m * 32 + mi * 16 + lq;
#pragma unroll
        for (int ni = 0; ni < 8; ni++) {
            int cg = col0 + warp_n * 64 + ni * 8 + 2 * lr;
            float bx = bias[cg], by = bias[cg + 1];
            float v00 = c[mi][ni][0] + bx, v01 = c[mi][ni][1] + by;
            float v10 = c[mi][ni][2] + bx, v11 = c[mi][ni][3] + by;
            if (MODE == 0) {
                if ((cg % 192) < 64) {     // q columns: pre-scale by 0.125
                    v00 *= 0.125f; v01 *= 0.125f; v10 *= 0.125f; v11 *= 0.125f;
                }
                __half* C = (__half*)Cv;
                *reinterpret_cast<uint32_t*>(C + (size_t)rg * N + cg)       = f22h2(v00, v01);
                *reinterpret_cast<uint32_t*>(C + (size_t)(rg + 8) * N + cg) = f22h2(v10, v11);
            } else {
                float* C = (float*)Cv;
                *reinterpret_cast<float2*>(C + (size_t)rg * N + cg)       = make_float2(v00, v01);
                *reinterpret_cast<float2*>(C + (size_t)(rg + 8) * N + cg) = make_float2(v10, v11);
            }
        }
    }
}

// ============================================================================
// fp16 flash attention, kv-tile 64 (half the barriers/softmax passes of R15).
// cp.async 2-stage K/V + ldmatrix (V via .trans). CTA: 8 warps, 128 q-rows.
// Stage: K [64][72] + V [64][72] halves = 18432 B; 2 stages = 36864 B static.
// Q staging [128][72] (18432 B) aliases the stage region.
// ============================================================================
#define QSTR 72
#define KVROWS 64
#define KVSTGH (2 * KVROWS * QSTR)      // halves per stage = 9216

__global__ __launch_bounds__(256) void attn_f16_kernel(const __half* __restrict__ qkv,
                                                       __half* __restrict__ att)
{
    __shared__ __half smh[2 * KVSTGH];   // 36864 B

    const int tid  = threadIdx.x;
    const int lane = tid & 31;
    const int w    = tid >> 5;
    const int lq   = lane >> 2;
    const int lr   = lane & 3;

    const int qt = blockIdx.x;
    const int bh = blockIdx.y;
    const int b  = bh >> 4;
    const int h  = bh & 15;

    const size_t rs = QKVCOLS;
    const __half* base = qkv + (size_t)b * SEQ * rs + h * (3 * HD);

    const int a_r = (lane & 7) + ((lane >> 3) & 1) * 8;
    const int a_c = (lane >> 4) * 8;
    const int b_r = (lane & 7) + (lane >> 4) * 8;
    const int b_c = ((lane >> 3) & 1) * 8;

    // ---- stage Q tile [128][64] halves (pre-scaled by GEMM1) ----
#pragma unroll
    for (int l = 0; l < 4; l++) {
        int f  = tid + l * 256;
        int r  = f >> 3;
        int ch = (f & 7) << 3;
        uint4 v = *reinterpret_cast<const uint4*>(base + (size_t)(qt * 128 + r) * rs + ch);
        *reinterpret_cast<uint4*>(smh + r * QSTR + ch) = v;
    }
    __syncthreads();

    uint32_t aq[4][4];
    {
        uint32_t qBase = smem_u32(smh);
#pragma unroll
        for (int kk = 0; kk < 4; kk++) {
            uint32_t addr = qBase + (uint32_t)((w * 16 + a_r) * QSTR + kk * 16 + a_c) * 2;
            LDSM_X4(aq[kk][0], aq[kk][1], aq[kk][2], aq[kk][3], addr);
        }
    }
    __syncthreads();    // Q consumed; smem reusable for K/V stages

    const uint32_t sb = smem_u32(smh);
    // stage loader: K 512 chunks + V 512 chunks over 256 threads (4 each)
    auto load_kv = [&](int stg, int kt) {
        uint32_t ks = sb + (uint32_t)stg * (KVSTGH * 2);
        uint32_t vs = ks + KVROWS * QSTR * 2;
#pragma unroll
        for (int l = 0; l < 2; l++) {
            int f  = tid + l * 256;       // 0..511
            int r  = f >> 3;              // 0..63
            int ch = (f & 7) << 3;        // 0..56
            const __half* src = base + 64 + (size_t)(kt * KVROWS + r) * rs + ch;
            uint32_t doff = (uint32_t)(r * QSTR + ch) * 2;
            CP_ASYNC16(ks + doff, src);
            CP_ASYNC16(vs + doff, src + 64);
        }
    };

    float o[8][4];
#pragma unroll
    for (int ni = 0; ni < 8; ni++)
#pragma unroll
        for (int j = 0; j < 4; j++) o[ni][j] = 0.f;
    float m0 = -INFINITY, m1 = -INFINITY, l0 = 0.f, l1 = 0.f;

    load_kv(0, 0);
    CP_COMMIT();

    const int NT = SEQ / KVROWS;         // 32
    for (int kt = 0; kt < NT; kt++) {
        const int buf = kt & 1;
        CP_WAIT0();
        __syncthreads();
        if (kt + 1 < NT) {
            load_kv(buf ^ 1, kt + 1);
            CP_COMMIT();
        }

        const uint32_t kBase = sb + (uint32_t)buf * (KVSTGH * 2);
        const uint32_t vBase = kBase + KVROWS * QSTR * 2;

        // ---- S = Q K^T : 8 n-subtiles (64 kv) x 4 k16-steps ----
        float s[8][4];
#pragma unroll
        for (int ni = 0; ni < 8; ni++)
#pragma unroll
            for (int j = 0; j < 4; j++) s[ni][j] = 0.f;

#pragma unroll
        for (int kk = 0; kk < 4; kk++) {
            uint32_t bk[8][2];
#pragma unroll
            for (int ni = 0; ni < 8; ni += 2) {
                uint32_t addr = kBase +
                    (uint32_t)((ni * 8 + b_r) * QSTR + kk * 16 + b_c) * 2;
                LDSM_X4(bk[ni][0], bk[ni][1], bk[ni + 1][0], bk[ni + 1][1], addr);
            }
#pragma unroll
            for (int ni = 0; ni < 8; ni++)
                MMA_F16(s[ni][0], s[ni][1], s[ni][2], s[ni][3],
                        aq[kk][0], aq[kk][1], aq[kk][2], aq[kk][3],
                        bk[ni][0], bk[ni][1]);
        }

        // ---- online softmax on fragments (rows lq, lq+8) ----
        float mx0 = -INFINITY, mx1 = -INFINITY;
#pragma unroll
        for (int ni = 0; ni < 8; ni++) {
            mx0 = fmaxf(mx0, fmaxf(s[ni][0], s[ni][1]));
            mx1 = fmaxf(mx1, fmaxf(s[ni][2], s[ni][3]));
        }
        mx0 = fmaxf(mx0, __shfl_xor_sync(0xffffffffu, mx0, 1));
        mx0 = fmaxf(mx0, __shfl_xor_sync(0xffffffffu, mx0, 2));
        mx1 = fmaxf(mx1, __shfl_xor_sync(0xffffffffu, mx1, 1));
        mx1 = fmaxf(mx1, __shfl_xor_sync(0xffffffffu, mx1, 2));

        float mn0 = fmaxf(m0, mx0);
        float mn1 = fmaxf(m1, mx1);
        float corr0 = __expf(m0 - mn0);
        float corr1 = __expf(m1 - mn1);
        m0 = mn0; m1 = mn1;

        float sum0 = 0.f, sum1 = 0.f;
#pragma unroll
        for (int ni = 0; ni < 8; ni++) {
            s[ni][0] = __expf(s[ni][0] - m0);
            s[ni][1] = __expf(s[ni][1] - m0);
            s[ni][2] = __expf(s[ni][2] - m1);
            s[ni][3] = __expf(s[ni][3] - m1);
            sum0 += s[ni][0] + s[ni][1];
            sum1 += s[ni][2] + s[ni][3];
        }
        sum0 += __shfl_xor_sync(0xffffffffu, sum0, 1);
        sum0 += __shfl_xor_sync(0xffffffffu, sum0, 2);
        sum1 += __shfl_xor_sync(0xffffffffu, sum1, 1);
        sum1 += __shfl_xor_sync(0xffffffffu, sum1, 2);
        l0 = l0 * corr0 + sum0;
        l1 = l1 * corr1 + sum1;

#pragma unroll
        for (int ni = 0; ni < 8; ni++) {
            o[ni][0] *= corr0; o[ni][1] *= corr0;
            o[ni][2] *= corr1; o[ni][3] *= corr1;
        }

        // ---- O += P V : P from own regs (fp16 trick), V via ldmatrix.trans
#pragma unroll
        for (int t = 0; t < 4; t++) {    // 4 k16-steps over 64 kv rows
            uint32_t pa0 = f22h2(s[2 * t][0],     s[2 * t][1]);
            uint32_t pa1 = f22h2(s[2 * t][2],     s[2 * t][3]);
            uint32_t pa2 = f22h2(s[2 * t + 1][0], s[2 * t + 1][1]);
            uint32_t pa3 = f22h2(s[2 * t + 1][2], s[2 * t + 1][3]);
            uint32_t vb[8][2];
#pragma unroll
            for (int ni = 0; ni < 8; ni += 2) {
                uint32_t addr = vBase +
                    (uint32_t)((t * 16 + a_r) * QSTR + ni * 8 + a_c) * 2;
                LDSM_X4_T(vb[ni][0], vb[ni][1], vb[ni + 1][0], vb[ni + 1][1], addr);
            }
#pragma unroll
            for (int ni = 0; ni < 8; ni++)
                MMA_F16(o[ni][0], o[ni][1], o[ni][2], o[ni][3],
                        pa0, pa1, pa2, pa3, vb[ni][0], vb[ni][1]);
        }
    }

    // ---- finalize + write att (fp16) ----
    float inv0 = 1.f / l0;
    float inv1 = 1.f / l1;
    int gq = qt * 128 + w * 16 + lq;
    __half* orow0 = att + (size_t)(b * SEQ + gq) * EMBED + h * HD;
    __half* orow1 = orow0 + (size_t)8 * EMBED;
#pragma unroll
    for (int ni = 0; ni < 8; ni++) {
        int col = ni * 8 + 2 * lr;
        *reinterpret_cast<uint32_t*>(orow0 + col) = f22h2(o[ni][0] * inv0, o[ni][1] * inv0);
        *reinterpret_cast<uint32_t*>(orow1 + col) = f22h2(o[ni][2] * inv1, o[ni][3] * inv1);
    }
}

// ---------------------------------------------------------------------------
extern "C" void kernel_launch(void* const* d_in, const int* in_sizes, int n_in,
                              void* d_out, int out_size)
{
    (void)in_sizes; (void)n_in; (void)out_size;
    const float* x     = (const float*)d_in[0];
    const float* qkv_w = (const float*)d_in[1];
    const float* qkv_b = (const float*)d_in[2];
    const float* out_w = (const float*)d_in[3];
    const float* out_b = (const float*)d_in[4];
    float* out = (float*)d_out;

    __half *qkv_buf, *att_buf, *xh, *wqkvh, *wouth;
    cudaGetSymbolAddress((void**)&qkv_buf, g_qkv);
    cudaGetSymbolAddress((void**)&att_buf, g_att);
    cudaGetSymbolAddress((void**)&xh, g_xh);
    cudaGetSymbolAddress((void**)&wqkvh, g_wqkvh);
    cudaGetSymbolAddress((void**)&wouth, g_wouth);

    // 0) pre-convert fp32 -> fp16
    cvt_f16_kernel<<<512, 256>>>(x, xh, ROWS * EMBED / 4);
    cvt_f16_kernel<<<512, 256>>>(qkv_w, wqkvh, QKVCOLS * EMBED / 4);
    cvt_f16_kernel<<<512, 256>>>(out_w, wouth, EMBED * EMBED / 4);

    // 1) qkv = x @ qkv_w^T + qkv_b  -> fp16, q cols pre-scaled
    gemm_f16_kernel<0><<<dim3(QKVCOLS / 128, ROWS / 128), 256>>>(
        xh, wqkvh, qkv_b, qkv_buf, ROWS, QKVCOLS, EMBED);

    // 2) attention -> att (fp16)
    attn_f16_kernel<<<dim3(SEQ / 128, BATCH * NHEADS), 256>>>(qkv_buf, att_buf);

    // 3) out = att @ out_w^T + out_b (fp32)
    gemm_f16_kernel<1><<<dim3(EMBED / 128, ROWS / 128), 256>>>(
        att_buf, wouth, out_b, out, ROWS, EMBED, EMBED);
}